// round 14
// baseline (speedup 1.0000x reference)
#include <cuda_runtime.h>
#include <cuda_fp16.h>
#include <math.h>
#include <stdint.h>

// Problem constants
#define BB   32
#define NN   64
#define NH   16
#define RR   1024
#define REP  1024
#define MM   1008
#define NCLS 117

// Output layout offsets (floats)
#define OFF_BH  66060288L
#define OFF_BO  66189312L
#define OFF_PR  66318336L

// ---------------- scratch (device globals) -----------------------------------
__device__ float g_encA[BB * NN * RR];
__device__ float g_encB[BB * NN * RR];
__device__ float g_UV [BB * NN * 2048];
__device__ float g_O  [BB * NN * REP];
__device__ float g_mh [BB * NH * REP];
__device__ float g_eh [BB * NH * RR];
__device__ float g_S  [BB * NH * REP];
__device__ float g_mo [BB * NN * REP];
__device__ float g_A  [BB * NH * NN];
__device__ float g_wsum[2 * BB * 1024];   // per-n-block partial W3 sums

// packed weights, interleaved-pair layout, fp16 hi/lo planes
__device__ uint32_t g_W1p [1024L * 2048];
__device__ uint32_t g_W2p [1024L * 512];
__device__ uint32_t g_Wop [1024L * 1024];
__device__ uint32_t g_Wsp [1024L * 1024];
__device__ uint32_t g_Wsup[2048L * 1024];
__device__ uint32_t g_Woup[2048L * 1024];

// ---------------- helpers ----------------------------------------------------
__device__ __forceinline__ void mma16(float* c, const uint32_t* a, const uint32_t* b)
{
    asm volatile(
        "mma.sync.aligned.m16n8k16.row.col.f32.f16.f16.f32 "
        "{%0,%1,%2,%3}, {%4,%5,%6,%7}, {%8,%9}, {%0,%1,%2,%3};\n"
        : "+f"(c[0]), "+f"(c[1]), "+f"(c[2]), "+f"(c[3])
        : "r"(a[0]), "r"(a[1]), "r"(a[2]), "r"(a[3]), "r"(b[0]), "r"(b[1]));
}

__device__ __forceinline__ uint32_t pk_hi(float x0, float x1)
{
    uint32_t r;
    asm("cvt.rn.f16x2.f32 %0, %1, %2;" : "=r"(r) : "f"(x1), "f"(x0));
    return r;
}
__device__ __forceinline__ uint32_t pk_lo(float x0, float x1, uint32_t hi)
{
    __half2 h = *reinterpret_cast<__half2*>(&hi);
    float l0 = x0 - __low2float(h);
    float l1 = x1 - __high2float(h);
    return pk_hi(l0, l1);
}

__device__ __forceinline__ void cpa16(void* smem, const void* gmem)
{
    uint32_t s = (uint32_t)__cvta_generic_to_shared(smem);
    asm volatile("cp.async.cg.shared.global [%0], [%1], 16;\n" :: "r"(s), "l"(gmem));
}
__device__ __forceinline__ void cp_commit()
{
    asm volatile("cp.async.commit_group;\n");
}
template <int N> __device__ __forceinline__ void cp_wait()
{
    asm volatile("cp.async.wait_group %0;\n" :: "n"(N));
}

// ---------------- weight prepack (interleaved-pair layout, fp16 planes) -------
__global__ __launch_bounds__(256) void pack_w(
    const float* __restrict__ W, uint32_t* __restrict__ Wp, int Kh, int N)
{
    const long plane = (long)Kh * N;
    const long total = 2 * plane;
    const int rowlen = 2 * N;
    for (long i = blockIdx.x * blockDim.x + threadIdx.x; i < total;
         i += (long)gridDim.x * blockDim.x) {
        int p = (int)(i / plane);
        long rem = i - (long)p * plane;
        int row = (int)(rem / rowlen);
        int col2 = (int)(rem - (long)row * rowlen);
        int n = col2 >> 1, j = col2 & 1;
        int q = row >> 2, tig = row & 3;
        int kp = q * 8 + tig + 4 * j;
        float x0 = W[(long)(2 * kp) * N + n];
        float x1 = W[(long)(2 * kp + 1) * N + n];
        uint32_t hi = pk_hi(x0, x1);
        Wp[i] = p ? pk_lo(x0, x1, hi) : hi;
    }
}

// fused UV pack: Wuv(k, c) = c<1024 ? W1[k][c] : W1[1024+k][c-1024]
__global__ __launch_bounds__(256) void pack_wuv(
    const float* __restrict__ W1, uint32_t* __restrict__ Wp)
{
    const long plane = 512L * 2048;
    const long total = 2 * plane;
    for (long i = blockIdx.x * blockDim.x + threadIdx.x; i < total;
         i += (long)gridDim.x * blockDim.x) {
        int p = (int)(i / plane);
        long rem = i - (long)p * plane;
        int row = (int)(rem >> 12);
        int col2 = (int)(rem & 4095);
        int n = col2 >> 1, j = col2 & 1;
        int q = row >> 2, tig = row & 3;
        int kp = q * 8 + tig + 4 * j;
        int k0 = 2 * kp, k1 = 2 * kp + 1;
        float x0, x1;
        if (n < 1024) {
            x0 = W1[(long)k0 * 1024 + n];
            x1 = W1[(long)k1 * 1024 + n];
        } else {
            x0 = W1[(long)(1024 + k0) * 1024 + (n - 1024)];
            x1 = W1[(long)(1024 + k1) * 1024 + (n - 1024)];
        }
        uint32_t hi = pk_hi(x0, x1);
        Wp[i] = p ? pk_lo(x0, x1, hi) : hi;
    }
}

// ---------------- batched GEMM (fp16 2-product, BM=128 x BN=128) --------------
// 512 threads (16 warps: 4m x 4n), 2 blocks/SM. Halves weight L2 traffic vs BM=64.
// smem: A [2][128][20]=5120 w; B [2][2][8][264]=8448 w.
#define GEMM_SMEM ((5120 + 8448) * 4)
__global__ __launch_bounds__(512, 2) void gemm_f16p(
    const float* __restrict__ A1, const float* __restrict__ A1o,
    int lrpb, long sA1, int K1,
    const float* __restrict__ A2, long sA2,
    const uint32_t* __restrict__ Wp, const float* __restrict__ bias,
    float* __restrict__ C, int Nw, long PKw, int ldc, int Ktot, int do_relu)
{
    extern __shared__ __align__(16) uint32_t sm[];
    uint32_t* As = sm;
    uint32_t* Bs = sm + 5120;

    const int t = threadIdx.x, lane = t & 31, warp = t >> 5;
    const int gid = lane >> 2, tig = lane & 3;
    const int wm = warp >> 2, wn = warp & 3;
    const int m0 = wm * 32, n0w = wn * 32;
    const long bn0 = (long)blockIdx.x * 128;
    const int bm0 = blockIdx.y * 128;
    const int K2 = Ktot - K1;
    const int rmask = (1 << lrpb) - 1;

    const int lrow = t >> 2, lf4 = t & 3;    // 128 rows, 4 threads/row
    const int grow = bm0 + lrow;
    const int b = grow >> lrpb, n = grow & rmask;
    const float* p1 = (A1o && n < 16)
                        ? (A1o + (long)b * 16384 + (long)n * 1024)
                        : (A1 + (long)b * sA1 + (long)n * K1);
    const float* p2 = A2 ? (A2 + (long)b * sA2 + (long)n * K2) : p1;

    float4 ra0, ra1;
    auto ldgA = [&](int k0) {
        const float* rp = (k0 < K1) ? (p1 + k0) : (p2 + (k0 - K1));
        ra0 = *(const float4*)(rp + lf4 * 4);
        ra1 = *(const float4*)(rp + lf4 * 4 + 16);
    };
    auto stsA = [&](int buf) {
        uint32_t* Ah = As + buf * 2560 + lrow * 20;
        const int w = lf4 * 2;
        Ah[w]     = pk_hi(ra0.x, ra0.y);
        Ah[w + 1] = pk_hi(ra0.z, ra0.w);
        Ah[w + 8] = pk_hi(ra1.x, ra1.y);
        Ah[w + 9] = pk_hi(ra1.z, ra1.w);
    };
    auto stageB = [&](int buf, int k0) {
        const int gr0 = k0 >> 2;
#pragma unroll
        for (int i = 0; i < 2; i++) {
            int f = t + i * 512;                 // 0..1023
            int plane = f >> 9, g = f & 511;
            int rl = g >> 6, c4 = (g & 63) * 4;
            cpa16(&Bs[buf * 4224 + plane * 2112 + rl * 264 + c4],
                  Wp + plane * PKw + (long)(gr0 + rl) * (2 * Nw) + bn0 * 2 + c4);
        }
        cp_commit();
    };

    float c[2][4][4];
#pragma unroll
    for (int mt = 0; mt < 2; mt++)
#pragma unroll
        for (int nt = 0; nt < 4; nt++)
#pragma unroll
            for (int e = 0; e < 4; e++) c[mt][nt][e] = 0.f;

    ldgA(0); stageB(0, 0); stsA(0);
    int buf = 0;
    for (int k0 = 0; k0 < Ktot; k0 += 32) {
        const bool more = (k0 + 32 < Ktot);
        cp_wait<0>();
        __syncthreads();
        if (more) { ldgA(k0 + 32); stageB(buf ^ 1, k0 + 32); }

        const uint32_t* Ah = As + buf * 2560;
        const uint32_t* Bh = Bs + buf * 4224;
        const uint32_t* Bl = Bh + 2112;
#pragma unroll
        for (int k16 = 0; k16 < 2; k16++) {
            const int kb = k16 * 8;
            uint32_t ah[2][4];
#pragma unroll
            for (int mt = 0; mt < 2; mt++) {
                int r0 = (m0 + mt * 16 + gid) * 20;
                int r1 = r0 + 160;
                ah[mt][0] = Ah[r0 + kb + tig];
                ah[mt][1] = Ah[r1 + kb + tig];
                ah[mt][2] = Ah[r0 + kb + tig + 4];
                ah[mt][3] = Ah[r1 + kb + tig + 4];
            }
            const int brow = (k16 * 4 + tig) * 264;
#pragma unroll
            for (int nt = 0; nt < 4; nt++) {
                int cw = brow + 2 * (n0w + nt * 8 + gid);
                uint2 b2h = *(const uint2*)&Bh[cw];
                uint2 b2l = *(const uint2*)&Bl[cw];
                uint32_t bh[2] = { b2h.x, b2h.y };
                uint32_t bl[2] = { b2l.x, b2l.y };
#pragma unroll
                for (int mt = 0; mt < 2; mt++) {
                    mma16(c[mt][nt], ah[mt], bh);
                    mma16(c[mt][nt], ah[mt], bl);
                }
            }
        }
        if (more) stsA(buf ^ 1);
        buf ^= 1;
    }

#pragma unroll
    for (int mt = 0; mt < 2; mt++) {
#pragma unroll
        for (int nt = 0; nt < 4; nt++) {
            long col = bn0 + n0w + nt * 8 + 2 * tig;
            float b0v = 0.f, b1v = 0.f;
            if (bias) { b0v = bias[col]; b1v = bias[col + 1]; }
            int r = bm0 + m0 + mt * 16 + gid;
            float v0 = c[mt][nt][0] + b0v, v1 = c[mt][nt][1] + b1v;
            float v2 = c[mt][nt][2] + b0v, v3 = c[mt][nt][3] + b1v;
            if (do_relu) {
                v0 = fmaxf(v0, 0.f); v1 = fmaxf(v1, 0.f);
                v2 = fmaxf(v2, 0.f); v3 = fmaxf(v3, 0.f);
            }
            *(float2*)&C[(long)r * ldc + col]       = make_float2(v0, v1);
            *(float2*)&C[(long)(r + 8) * ldc + col] = make_float2(v2, v3);
        }
    }
}

// ---------------- fused pair MLP (fp16 2-product, BM=128 x BN=256) ------------
// grid (8 mblk, 2 nblk, 32 batches), 512 threads (16 warps: 4m x 4n).
// smem: A [2][128][20]=5120 w; B [2][2][8][520]=16640 w; wpart 512 w; b1s 1024 w.
#define PAIR_SMEM ((5120 + 16640 + 512 + 1024) * 4)
__global__ __launch_bounds__(512, 1) void pair_mlp_mma(
    const float* __restrict__ UV, const float* __restrict__ b1,
    const uint32_t* __restrict__ W2p, const float* __restrict__ b2,
    const float* __restrict__ W3, float* __restrict__ wsum)
{
    extern __shared__ __align__(16) uint32_t sm[];
    uint32_t* As = sm;
    uint32_t* Bs = sm + 5120;
    float* wpart = (float*)(sm + 5120 + 16640);
    float* b1s   = (float*)(sm + 5120 + 16640 + 512);

    const int t = threadIdx.x, lane = t & 31, warp = t >> 5;
    const int gid = lane >> 2, tig = lane & 3;
    const int wm = warp >> 2, wn = warp & 3;
    const int m0 = wm * 32, n0w = wn * 64;
    const int mblk = blockIdx.x, nblk = blockIdx.y, bi = blockIdx.z;
    const int n0blk = nblk * 256;
    const long PK2 = 512L * 512;

    b1s[t] = b1[t];
    b1s[t + 512] = b1[t + 512];
    __syncthreads();

    const int lrow = t >> 2, lf4 = t & 3;
    const int mld = mblk * 128 + lrow;
    const int valid = (mld < MM);
    int xl = 0, yl = 0;
    if (valid) { xl = mld / 63; int rl = mld - 63 * xl; yl = rl + (rl >= xl ? 1 : 0); }
    const float* Urow = UV + ((long)(bi * 64 + xl)) * 2048;
    const float* Vrow = UV + ((long)(bi * 64 + yl)) * 2048 + 1024;

    float4 ru0, ru1, rv0, rv1;
    auto ldgA = [&](int k0) {
        ru0 = *(const float4*)(Urow + k0 + lf4 * 4);
        ru1 = *(const float4*)(Urow + k0 + lf4 * 4 + 16);
        rv0 = *(const float4*)(Vrow + k0 + lf4 * 4);
        rv1 = *(const float4*)(Vrow + k0 + lf4 * 4 + 16);
    };
    auto stsA = [&](int buf, int k0) {
        float4 rb0 = *(const float4*)&b1s[k0 + lf4 * 4];
        float4 rb1 = *(const float4*)&b1s[k0 + lf4 * 4 + 16];
        float4 h0, h1;
        h0.x = fmaxf(ru0.x + rv0.x + rb0.x, 0.f);
        h0.y = fmaxf(ru0.y + rv0.y + rb0.y, 0.f);
        h0.z = fmaxf(ru0.z + rv0.z + rb0.z, 0.f);
        h0.w = fmaxf(ru0.w + rv0.w + rb0.w, 0.f);
        h1.x = fmaxf(ru1.x + rv1.x + rb1.x, 0.f);
        h1.y = fmaxf(ru1.y + rv1.y + rb1.y, 0.f);
        h1.z = fmaxf(ru1.z + rv1.z + rb1.z, 0.f);
        h1.w = fmaxf(ru1.w + rv1.w + rb1.w, 0.f);
        if (!valid) {
            h0 = make_float4(0.f, 0.f, 0.f, 0.f);
            h1 = make_float4(0.f, 0.f, 0.f, 0.f);
        }
        uint32_t* Ah = As + buf * 2560 + lrow * 20;
        const int w = lf4 * 2;
        Ah[w]     = pk_hi(h0.x, h0.y);
        Ah[w + 1] = pk_hi(h0.z, h0.w);
        Ah[w + 8] = pk_hi(h1.x, h1.y);
        Ah[w + 9] = pk_hi(h1.z, h1.w);
    };
    auto stageB = [&](int buf, int k0) {
        const int gr0 = k0 >> 2;
#pragma unroll
        for (int i = 0; i < 4; i++) {
            int f = t + i * 512;                // 0..2047
            int plane = f >> 10, g = f & 1023;
            int rl = g >> 7, c4 = (g & 127) * 4;
            cpa16(&Bs[buf * 8320 + plane * 4160 + rl * 520 + c4],
                  W2p + plane * PK2 + (long)(gr0 + rl) * 1024 + n0blk * 2 + c4);
        }
        cp_commit();
    };

    float c[2][8][4];
#pragma unroll
    for (int mt = 0; mt < 2; mt++)
#pragma unroll
        for (int nt = 0; nt < 8; nt++)
#pragma unroll
            for (int e = 0; e < 4; e++) c[mt][nt][e] = 0.f;

    ldgA(0); stageB(0, 0); stsA(0, 0);
    int buf = 0;
    for (int k0 = 0; k0 < REP; k0 += 32) {
        const bool more = (k0 + 32 < REP);
        cp_wait<0>();
        __syncthreads();
        if (more) { ldgA(k0 + 32); stageB(buf ^ 1, k0 + 32); }

        const uint32_t* Ah = As + buf * 2560;
        const uint32_t* Bh = Bs + buf * 8320;
        const uint32_t* Bl = Bh + 4160;
#pragma unroll
        for (int k16 = 0; k16 < 2; k16++) {
            const int kb = k16 * 8;
            uint32_t ah[2][4];
#pragma unroll
            for (int mt = 0; mt < 2; mt++) {
                int r0 = (m0 + mt * 16 + gid) * 20;
                int r1 = r0 + 160;
                ah[mt][0] = Ah[r0 + kb + tig];
                ah[mt][1] = Ah[r1 + kb + tig];
                ah[mt][2] = Ah[r0 + kb + tig + 4];
                ah[mt][3] = Ah[r1 + kb + tig + 4];
            }
            const int brow = (k16 * 4 + tig) * 520;
#pragma unroll
            for (int nt = 0; nt < 8; nt++) {
                int cw = brow + 2 * (n0w + nt * 8 + gid);
                uint2 b2h = *(const uint2*)&Bh[cw];
                uint2 b2l = *(const uint2*)&Bl[cw];
                uint32_t bh[2] = { b2h.x, b2h.y };
                uint32_t bl[2] = { b2l.x, b2l.y };
#pragma unroll
                for (int mt = 0; mt < 2; mt++) {
                    mma16(c[mt][nt], ah[mt], bh);
                    mma16(c[mt][nt], ah[mt], bl);
                }
            }
        }
        if (more) stsA(buf ^ 1, k0 + 32);
        buf ^= 1;
    }

    float rp[4] = { 0.f, 0.f, 0.f, 0.f };
#pragma unroll
    for (int mt = 0; mt < 2; mt++) {
#pragma unroll
        for (int nt = 0; nt < 8; nt++) {
            int col = n0blk + n0w + nt * 8 + 2 * tig;
            float b2a = b2[col], b2b = b2[col + 1];
            float w3a = W3[col], w3b = W3[col + 1];
            rp[2 * mt + 0] += fmaxf(c[mt][nt][0] + b2a, 0.f) * w3a
                            + fmaxf(c[mt][nt][1] + b2b, 0.f) * w3b;
            rp[2 * mt + 1] += fmaxf(c[mt][nt][2] + b2a, 0.f) * w3a
                            + fmaxf(c[mt][nt][3] + b2b, 0.f) * w3b;
        }
    }
#pragma unroll
    for (int e = 0; e < 4; e++) {
        float v = rp[e];
        v += __shfl_xor_sync(0xffffffffu, v, 1);
        v += __shfl_xor_sync(0xffffffffu, v, 2);
        int mt = e >> 1, o = e & 1;
        if (tig == 0) wpart[(m0 + mt * 16 + o * 8 + gid) * 4 + wn] = v;
    }
    __syncthreads();
    if (t < 128) {
        float s = wpart[t * 4 + 0] + wpart[t * 4 + 1]
                + wpart[t * 4 + 2] + wpart[t * 4 + 3];
        wsum[(long)nblk * (BB * 1024) + bi * 1024 + mblk * 128 + t] = s;
    }
}

// ---------------- sigmoid over summed W3 partials ------------------------------
__global__ __launch_bounds__(1024) void sigmoid_k(
    const float* __restrict__ wsum, const float* __restrict__ b3,
    float* __restrict__ Aout)
{
    const int bi = blockIdx.x, m = threadIdx.x;
    if (m < MM) {
        float s = wsum[bi * 1024 + m] + wsum[BB * 1024 + bi * 1024 + m] + b3[0];
        int x = m / 63; int r = m - 63 * x; int y = r + (r >= x ? 1 : 0);
        Aout[(bi * 16 + x) * 64 + y] = 1.f / (1.f + expf(-s));
    }
}

// ---------------- msg_h = A @ O ------------------------------------------------
__global__ __launch_bounds__(256) void msg_h_k(
    const float* __restrict__ Ag, const float* __restrict__ O, float* __restrict__ mh)
{
    __shared__ float As[NH * NN];
    const int b = blockIdx.y, t = threadIdx.x;
#pragma unroll
    for (int i = 0; i < 4; i++) As[t + 256 * i] = Ag[b * NH * NN + t + 256 * i];
    __syncthreads();
    const int j = blockIdx.x * 256 + t;
    float acc[NH];
#pragma unroll
    for (int x = 0; x < NH; x++) acc[x] = 0.f;
    for (int n = 0; n < NN; n++) {
        float o = O[((long)(b * NN + n)) * 1024 + j];
#pragma unroll
        for (int x = 0; x < NH; x++) acc[x] += As[x * NN + n] * o;
    }
#pragma unroll
    for (int x = 0; x < NH; x++) mh[((long)(b * NH + x)) * 1024 + j] = acc[x];
}

// ---------------- msg_o = A^T @ S ----------------------------------------------
__global__ __launch_bounds__(256) void msg_o_k(
    const float* __restrict__ Ag, const float* __restrict__ Sm, float* __restrict__ mo)
{
    __shared__ float As[NH * NN];
    const int b = blockIdx.y, t = threadIdx.x;
#pragma unroll
    for (int i = 0; i < 4; i++) As[t + 256 * i] = Ag[b * NH * NN + t + 256 * i];
    __syncthreads();
    const int j = blockIdx.x * 256 + t;
    float s[NH];
#pragma unroll
    for (int x = 0; x < NH; x++) s[x] = Sm[((long)(b * NH + x)) * 1024 + j];
    for (int n = 0; n < NN; n++) {
        float acc = 0.f;
#pragma unroll
        for (int x = 0; x < NH; x++) acc += As[x * NN + n] * s[x];
        mo[((long)(b * NN + n)) * 1024 + j] = acc;
    }
}

// ---------------- output assembly ----------------------------------------------
__device__ __forceinline__ float lis_f(float s) {
    return 8.3f / (1.f + expf(12.f - 10.f * s));
}

__global__ __launch_bounds__(128) void out_kernel(
    const float* __restrict__ enc, const float* __restrict__ Ag,
    const float* __restrict__ coords, const int* __restrict__ labels,
    const float* __restrict__ scores, float* __restrict__ out)
{
    const int b = blockIdx.y, m = blockIdx.x, t = threadIdx.x;
    const int x = m / 63; const int r = m - 63 * x; const int y = r + (r >= x ? 1 : 0);
    const long row = (long)b * MM + m;

    const float4* ex = (const float4*)(enc + ((long)(b * NN + x)) * RR);
    const float4* ey = (const float4*)(enc + ((long)(b * NN + y)) * RR);
    float4* po = (float4*)(out + row * 2048);
#pragma unroll
    for (int i = 0; i < 4; i++) {
        int q = t + (i << 7);
        po[q] = (q < 256) ? ex[q] : ey[q - 256];
    }
    if (t < 4)        out[OFF_BH + row * 4 + t]       = coords[(b * NN + x) * 4 + t];
    else if (t < 8)   out[OFF_BO + row * 4 + (t - 4)] = coords[(b * NN + y) * 4 + (t - 4)];

    const int lbl = labels[b * NN + y];
    const float val = Ag[(b * NH + x) * NN + y] *
                      lis_f(scores[b * NN + x]) * lis_f(scores[b * NN + y]);
    for (int c = t; c < NCLS; c += 128)
        out[OFF_PR + row * (long)NCLS + c] = (c == lbl) ? val : 0.f;
}

// ---------------- host orchestration -------------------------------------------
extern "C" void kernel_launch(void* const* d_in, const int* in_sizes, int n_in,
                              void* d_out, int out_size)
{
    const float* box_features = (const float*)d_in[0];
    const float* box_coords   = (const float*)d_in[1];
    const int*   box_labels   = (const int*)  d_in[2];
    const float* box_scores   = (const float*)d_in[3];
    const float* W1  = (const float*)d_in[4];
    const float* b1  = (const float*)d_in[5];
    const float* W2  = (const float*)d_in[6];
    const float* b2  = (const float*)d_in[7];
    const float* W3  = (const float*)d_in[8];
    const float* b3  = (const float*)d_in[9];
    const float* Ws  = (const float*)d_in[10];
    const float* bs  = (const float*)d_in[11];
    const float* Wo  = (const float*)d_in[12];
    const float* bo  = (const float*)d_in[13];
    const float* Wsu = (const float*)d_in[14];
    const float* Wou = (const float*)d_in[15];
    float* out = (float*)d_out;

    float *encA, *encB, *UV, *O, *mh, *eh, *Sb, *mo, *Ag, *wsum;
    uint32_t *W1p, *W2p, *Wop, *Wsp, *Wsup, *Woup;
    cudaGetSymbolAddress((void**)&encA, g_encA);
    cudaGetSymbolAddress((void**)&encB, g_encB);
    cudaGetSymbolAddress((void**)&UV,   g_UV);
    cudaGetSymbolAddress((void**)&O,    g_O);
    cudaGetSymbolAddress((void**)&mh,   g_mh);
    cudaGetSymbolAddress((void**)&eh,   g_eh);
    cudaGetSymbolAddress((void**)&Sb,   g_S);
    cudaGetSymbolAddress((void**)&mo,   g_mo);
    cudaGetSymbolAddress((void**)&Ag,   g_A);
    cudaGetSymbolAddress((void**)&wsum, g_wsum);
    cudaGetSymbolAddress((void**)&W1p,  g_W1p);
    cudaGetSymbolAddress((void**)&W2p,  g_W2p);
    cudaGetSymbolAddress((void**)&Wop,  g_Wop);
    cudaGetSymbolAddress((void**)&Wsp,  g_Wsp);
    cudaGetSymbolAddress((void**)&Wsup, g_Wsup);
    cudaGetSymbolAddress((void**)&Woup, g_Woup);

    cudaFuncSetAttribute(gemm_f16p,
                         cudaFuncAttributeMaxDynamicSharedMemorySize, GEMM_SMEM);
    cudaFuncSetAttribute(pair_mlp_mma,
                         cudaFuncAttributeMaxDynamicSharedMemorySize, PAIR_SMEM);

    // aux stream + events (created per call; never destroyed during capture)
    cudaStream_t s1;
    cudaStreamCreateWithFlags(&s1, cudaStreamNonBlocking);
    cudaEvent_t ev[6];
    for (int i = 0; i < 6; i++)
        cudaEventCreateWithFlags(&ev[i], cudaEventDisableTiming);

    // ---- prepack, split across streams ----
    cudaEventRecord(ev[0], 0);
    cudaStreamWaitEvent(s1, ev[0], 0);
    pack_wuv<<<512, 256>>>(W1, W1p);
    pack_w<<<256, 256>>>(Wo,  Wop,  512, 1024);
    pack_w<<<512, 256>>>(Wsu, Wsup, 1024, 1024);
    pack_w<<<256, 256, 0, s1>>>(W2, W2p, 512, 512);
    pack_w<<<256, 256, 0, s1>>>(Ws, Wsp, 512, 1024);
    pack_w<<<512, 256, 0, s1>>>(Wou, Woup, 1024, 1024);
    cudaMemcpyAsync(encA, box_features, (size_t)BB * NN * RR * 4,
                    cudaMemcpyDeviceToDevice, s1);
    cudaEventRecord(ev[1], s1);
    cudaStreamWaitEvent(0, ev[1], 0);

    const long sEnc = (long)NN * RR;   // 65536
    const long sH   = (long)NH * RR;   // 16384
    const float* NUL = (const float*)0;

    for (int it = 0; it < 2; it++) {
        float* encIn  = (it == 0) ? encA : encB;
        float* encOut = (it == 0) ? encB : encA;
        cudaEvent_t evF = ev[2 + 2 * it], evJ = ev[3 + 2 * it];

        // fork: O gemm on s1 (depends only on encIn)
        cudaEventRecord(evF, 0);
        cudaStreamWaitEvent(s1, evF, 0);
        gemm_f16p<<<dim3(8, 16), 512, GEMM_SMEM, s1>>>(
            encIn, NUL, 6, sEnc, 1024, NUL, 0,
            Wop, bo, O, 1024, 512L * 1024, 1024, 1024, 1);

        // s0: UV gemm -> pair MLP -> sigmoid
        gemm_f16p<<<dim3(16, 16), 512, GEMM_SMEM>>>(
            encIn, NUL, 6, sEnc, 1024, NUL, 0,
            W1p, NUL, UV, 2048, 512L * 2048, 2048, 1024, 0);
        pair_mlp_mma<<<dim3(8, 2, BB), 512, PAIR_SMEM>>>(
            UV, b1, W2p, b2, W3, wsum);
        sigmoid_k<<<BB, 1024>>>(wsum, b3, Ag);

        // join before msg_h (needs A and O)
        cudaEventRecord(evJ, s1);
        cudaStreamWaitEvent(0, evJ, 0);

        msg_h_k<<<dim3(4, BB), 256>>>(Ag, O, mh);
        gemm_f16p<<<dim3(8, 4), 512, GEMM_SMEM>>>(
            encIn, NUL, 4, sEnc, 1024, mh, sH,
            Wsup, NUL, eh, 1024, 1024L * 1024, 1024, 2048, 0);
        gemm_f16p<<<dim3(8, 4), 512, GEMM_SMEM>>>(
            eh, NUL, 4, sH, 1024, NUL, 0,
            Wsp, bs, Sb, 1024, 512L * 1024, 1024, 1024, 1);
        msg_o_k<<<dim3(4, BB), 256>>>(Ag, Sb, mo);
        // splice handled via A1o override: rows n<16 read eh instead of encIn
        gemm_f16p<<<dim3(8, 16), 512, GEMM_SMEM>>>(
            encIn, eh, 6, sEnc, 1024, mo, sEnc,
            Woup, NUL, encOut, 1024, 1024L * 1024, 1024, 2048, 0);
    }

    out_kernel<<<dim3(MM, BB), 128>>>(encA, Ag, box_coords, box_labels,
                                      box_scores, out);
    (void)in_sizes; (void)n_in; (void)out_size;
}

// round 15
// speedup vs baseline: 1.0847x; 1.0847x over previous
#include <cuda_runtime.h>
#include <cuda_fp16.h>
#include <math.h>
#include <stdint.h>

// Problem constants
#define BB   32
#define NN   64
#define NH   16
#define RR   1024
#define REP  1024
#define MM   1008
#define NCLS 117

// Output layout offsets (floats)
#define OFF_BH  66060288L
#define OFF_BO  66189312L
#define OFF_PR  66318336L

// ---------------- scratch (device globals) -----------------------------------
__device__ float g_encA[BB * NN * RR];
__device__ float g_encB[BB * NN * RR];
__device__ float g_UV [BB * NN * 2048];
__device__ float g_O  [BB * NN * REP];
__device__ float g_mh [BB * NH * REP];
__device__ float g_eh [BB * NH * RR];
__device__ float g_S  [BB * NH * REP];
__device__ float g_mo [BB * NN * REP];
__device__ float g_A  [BB * NH * NN];
__device__ float g_wsum[2 * BB * 1024];   // per-n-block partial W3 sums

// packed weights, interleaved-pair layout, fp16 hi/lo planes
__device__ uint32_t g_W1p [1024L * 2048];
__device__ uint32_t g_W2p [1024L * 512];
__device__ uint32_t g_Wop [1024L * 1024];
__device__ uint32_t g_Wsp [1024L * 1024];
__device__ uint32_t g_Wsup[2048L * 1024];
__device__ uint32_t g_Woup[2048L * 1024];

// ---------------- helpers ----------------------------------------------------
__device__ __forceinline__ void mma16(float* c, const uint32_t* a, const uint32_t* b)
{
    asm volatile(
        "mma.sync.aligned.m16n8k16.row.col.f32.f16.f16.f32 "
        "{%0,%1,%2,%3}, {%4,%5,%6,%7}, {%8,%9}, {%0,%1,%2,%3};\n"
        : "+f"(c[0]), "+f"(c[1]), "+f"(c[2]), "+f"(c[3])
        : "r"(a[0]), "r"(a[1]), "r"(a[2]), "r"(a[3]), "r"(b[0]), "r"(b[1]));
}

__device__ __forceinline__ uint32_t pk_hi(float x0, float x1)
{
    uint32_t r;
    asm("cvt.rn.f16x2.f32 %0, %1, %2;" : "=r"(r) : "f"(x1), "f"(x0));
    return r;
}
__device__ __forceinline__ uint32_t pk_lo(float x0, float x1, uint32_t hi)
{
    __half2 h = *reinterpret_cast<__half2*>(&hi);
    float l0 = x0 - __low2float(h);
    float l1 = x1 - __high2float(h);
    return pk_hi(l0, l1);
}

__device__ __forceinline__ void cpa16(void* smem, const void* gmem)
{
    uint32_t s = (uint32_t)__cvta_generic_to_shared(smem);
    asm volatile("cp.async.cg.shared.global [%0], [%1], 16;\n" :: "r"(s), "l"(gmem));
}
__device__ __forceinline__ void cp_commit()
{
    asm volatile("cp.async.commit_group;\n");
}
template <int N> __device__ __forceinline__ void cp_wait()
{
    asm volatile("cp.async.wait_group %0;\n" :: "n"(N));
}

// ---------------- weight prepack (interleaved-pair layout, fp16 planes) -------
__global__ __launch_bounds__(256) void pack_w(
    const float* __restrict__ W, uint32_t* __restrict__ Wp, int Kh, int N)
{
    const long plane = (long)Kh * N;
    const long total = 2 * plane;
    const int rowlen = 2 * N;
    for (long i = blockIdx.x * blockDim.x + threadIdx.x; i < total;
         i += (long)gridDim.x * blockDim.x) {
        int p = (int)(i / plane);
        long rem = i - (long)p * plane;
        int row = (int)(rem / rowlen);
        int col2 = (int)(rem - (long)row * rowlen);
        int n = col2 >> 1, j = col2 & 1;
        int q = row >> 2, tig = row & 3;
        int kp = q * 8 + tig + 4 * j;
        float x0 = W[(long)(2 * kp) * N + n];
        float x1 = W[(long)(2 * kp + 1) * N + n];
        uint32_t hi = pk_hi(x0, x1);
        Wp[i] = p ? pk_lo(x0, x1, hi) : hi;
    }
}

// fused UV pack: Wuv(k, c) = c<1024 ? W1[k][c] : W1[1024+k][c-1024]
__global__ __launch_bounds__(256) void pack_wuv(
    const float* __restrict__ W1, uint32_t* __restrict__ Wp)
{
    const long plane = 512L * 2048;
    const long total = 2 * plane;
    for (long i = blockIdx.x * blockDim.x + threadIdx.x; i < total;
         i += (long)gridDim.x * blockDim.x) {
        int p = (int)(i / plane);
        long rem = i - (long)p * plane;
        int row = (int)(rem >> 12);
        int col2 = (int)(rem & 4095);
        int n = col2 >> 1, j = col2 & 1;
        int q = row >> 2, tig = row & 3;
        int kp = q * 8 + tig + 4 * j;
        int k0 = 2 * kp, k1 = 2 * kp + 1;
        float x0, x1;
        if (n < 1024) {
            x0 = W1[(long)k0 * 1024 + n];
            x1 = W1[(long)k1 * 1024 + n];
        } else {
            x0 = W1[(long)(1024 + k0) * 1024 + (n - 1024)];
            x1 = W1[(long)(1024 + k1) * 1024 + (n - 1024)];
        }
        uint32_t hi = pk_hi(x0, x1);
        Wp[i] = p ? pk_lo(x0, x1, hi) : hi;
    }
}

// ---------------- batched GEMM (fp16 2-product, BM=64 x BN=128) ---------------
// R13 winner configuration. 256 threads, 2 blocks/SM.
#define GEMM_SMEM ((2560 + 8448) * 4)
__global__ __launch_bounds__(256, 2) void gemm_f16p(
    const float* __restrict__ A1, const float* __restrict__ A1o,
    int lrpb, long sA1, int K1,
    const float* __restrict__ A2, long sA2,
    const uint32_t* __restrict__ Wp, const float* __restrict__ bias,
    float* __restrict__ C, int Nw, long PKw, int ldc, int Ktot, int do_relu)
{
    extern __shared__ __align__(16) uint32_t sm[];
    uint32_t* As = sm;
    uint32_t* Bs = sm + 2560;

    const int t = threadIdx.x, lane = t & 31, warp = t >> 5;
    const int gid = lane >> 2, tig = lane & 3;
    const int wm = warp >> 2, wn = warp & 3;
    const int m0 = wm * 32, n0w = wn * 32;
    const long bn0 = (long)blockIdx.x * 128;
    const int bm0 = blockIdx.y * 64;
    const int K2 = Ktot - K1;
    const int rmask = (1 << lrpb) - 1;

    const int lrow = t >> 2, lf4 = t & 3;
    const int grow = bm0 + lrow;
    const int b = grow >> lrpb, n = grow & rmask;
    const float* p1 = (A1o && n < 16)
                        ? (A1o + (long)b * 16384 + (long)n * 1024)
                        : (A1 + (long)b * sA1 + (long)n * K1);
    const float* p2 = A2 ? (A2 + (long)b * sA2 + (long)n * K2) : p1;

    float4 ra0, ra1;
    auto ldgA = [&](int k0) {
        const float* rp = (k0 < K1) ? (p1 + k0) : (p2 + (k0 - K1));
        ra0 = *(const float4*)(rp + lf4 * 4);
        ra1 = *(const float4*)(rp + lf4 * 4 + 16);
    };
    auto stsA = [&](int buf) {
        uint32_t* Ah = As + buf * 1280 + lrow * 20;
        const int w = lf4 * 2;
        Ah[w]     = pk_hi(ra0.x, ra0.y);
        Ah[w + 1] = pk_hi(ra0.z, ra0.w);
        Ah[w + 8] = pk_hi(ra1.x, ra1.y);
        Ah[w + 9] = pk_hi(ra1.z, ra1.w);
    };
    auto stageB = [&](int buf, int k0) {
        const int gr0 = k0 >> 2;
#pragma unroll
        for (int i = 0; i < 4; i++) {
            int f = t + i * 256;
            int plane = f >> 9, g = f & 511;
            int rl = g >> 6, c4 = (g & 63) * 4;
            cpa16(&Bs[buf * 4224 + plane * 2112 + rl * 264 + c4],
                  Wp + plane * PKw + (long)(gr0 + rl) * (2 * Nw) + bn0 * 2 + c4);
        }
        cp_commit();
    };

    float c[2][4][4];
#pragma unroll
    for (int mt = 0; mt < 2; mt++)
#pragma unroll
        for (int nt = 0; nt < 4; nt++)
#pragma unroll
            for (int e = 0; e < 4; e++) c[mt][nt][e] = 0.f;

    ldgA(0); stageB(0, 0); stsA(0);
    int buf = 0;
    for (int k0 = 0; k0 < Ktot; k0 += 32) {
        const bool more = (k0 + 32 < Ktot);
        cp_wait<0>();
        __syncthreads();
        if (more) { ldgA(k0 + 32); stageB(buf ^ 1, k0 + 32); }

        const uint32_t* Ah = As + buf * 1280;
        const uint32_t* Bh = Bs + buf * 4224;
        const uint32_t* Bl = Bh + 2112;
#pragma unroll
        for (int k16 = 0; k16 < 2; k16++) {
            const int kb = k16 * 8;
            uint32_t ah[2][4];
#pragma unroll
            for (int mt = 0; mt < 2; mt++) {
                int r0 = (m0 + mt * 16 + gid) * 20;
                int r1 = r0 + 160;
                ah[mt][0] = Ah[r0 + kb + tig];
                ah[mt][1] = Ah[r1 + kb + tig];
                ah[mt][2] = Ah[r0 + kb + tig + 4];
                ah[mt][3] = Ah[r1 + kb + tig + 4];
            }
            const int brow = (k16 * 4 + tig) * 264;
#pragma unroll
            for (int nt = 0; nt < 4; nt++) {
                int cw = brow + 2 * (n0w + nt * 8 + gid);
                uint2 b2h = *(const uint2*)&Bh[cw];
                uint2 b2l = *(const uint2*)&Bl[cw];
                uint32_t bh[2] = { b2h.x, b2h.y };
                uint32_t bl[2] = { b2l.x, b2l.y };
#pragma unroll
                for (int mt = 0; mt < 2; mt++) {
                    mma16(c[mt][nt], ah[mt], bh);
                    mma16(c[mt][nt], ah[mt], bl);
                }
            }
        }
        if (more) stsA(buf ^ 1);
        buf ^= 1;
    }

#pragma unroll
    for (int mt = 0; mt < 2; mt++) {
#pragma unroll
        for (int nt = 0; nt < 4; nt++) {
            long col = bn0 + n0w + nt * 8 + 2 * tig;
            float b0v = 0.f, b1v = 0.f;
            if (bias) { b0v = bias[col]; b1v = bias[col + 1]; }
            int r = bm0 + m0 + mt * 16 + gid;
            float v0 = c[mt][nt][0] + b0v, v1 = c[mt][nt][1] + b1v;
            float v2 = c[mt][nt][2] + b0v, v3 = c[mt][nt][3] + b1v;
            if (do_relu) {
                v0 = fmaxf(v0, 0.f); v1 = fmaxf(v1, 0.f);
                v2 = fmaxf(v2, 0.f); v3 = fmaxf(v3, 0.f);
            }
            *(float2*)&C[(long)r * ldc + col]       = make_float2(v0, v1);
            *(float2*)&C[(long)(r + 8) * ldc + col] = make_float2(v2, v3);
        }
    }
}

// ---------------- fused pair MLP (fp16 2-product, BM=128 x BN=256) ------------
// R13 winner. grid (8, 2, 32), 512 threads.
#define PAIR_SMEM ((5120 + 16640 + 512 + 1024) * 4)
__global__ __launch_bounds__(512, 1) void pair_mlp_mma(
    const float* __restrict__ UV, const float* __restrict__ b1,
    const uint32_t* __restrict__ W2p, const float* __restrict__ b2,
    const float* __restrict__ W3, float* __restrict__ wsum)
{
    extern __shared__ __align__(16) uint32_t sm[];
    uint32_t* As = sm;
    uint32_t* Bs = sm + 5120;
    float* wpart = (float*)(sm + 5120 + 16640);
    float* b1s   = (float*)(sm + 5120 + 16640 + 512);

    const int t = threadIdx.x, lane = t & 31, warp = t >> 5;
    const int gid = lane >> 2, tig = lane & 3;
    const int wm = warp >> 2, wn = warp & 3;
    const int m0 = wm * 32, n0w = wn * 64;
    const int mblk = blockIdx.x, nblk = blockIdx.y, bi = blockIdx.z;
    const int n0blk = nblk * 256;
    const long PK2 = 512L * 512;

    b1s[t] = b1[t];
    b1s[t + 512] = b1[t + 512];
    __syncthreads();

    const int lrow = t >> 2, lf4 = t & 3;
    const int mld = mblk * 128 + lrow;
    const int valid = (mld < MM);
    int xl = 0, yl = 0;
    if (valid) { xl = mld / 63; int rl = mld - 63 * xl; yl = rl + (rl >= xl ? 1 : 0); }
    const float* Urow = UV + ((long)(bi * 64 + xl)) * 2048;
    const float* Vrow = UV + ((long)(bi * 64 + yl)) * 2048 + 1024;

    float4 ru0, ru1, rv0, rv1;
    auto ldgA = [&](int k0) {
        ru0 = *(const float4*)(Urow + k0 + lf4 * 4);
        ru1 = *(const float4*)(Urow + k0 + lf4 * 4 + 16);
        rv0 = *(const float4*)(Vrow + k0 + lf4 * 4);
        rv1 = *(const float4*)(Vrow + k0 + lf4 * 4 + 16);
    };
    auto stsA = [&](int buf, int k0) {
        float4 rb0 = *(const float4*)&b1s[k0 + lf4 * 4];
        float4 rb1 = *(const float4*)&b1s[k0 + lf4 * 4 + 16];
        float4 h0, h1;
        h0.x = fmaxf(ru0.x + rv0.x + rb0.x, 0.f);
        h0.y = fmaxf(ru0.y + rv0.y + rb0.y, 0.f);
        h0.z = fmaxf(ru0.z + rv0.z + rb0.z, 0.f);
        h0.w = fmaxf(ru0.w + rv0.w + rb0.w, 0.f);
        h1.x = fmaxf(ru1.x + rv1.x + rb1.x, 0.f);
        h1.y = fmaxf(ru1.y + rv1.y + rb1.y, 0.f);
        h1.z = fmaxf(ru1.z + rv1.z + rb1.z, 0.f);
        h1.w = fmaxf(ru1.w + rv1.w + rb1.w, 0.f);
        if (!valid) {
            h0 = make_float4(0.f, 0.f, 0.f, 0.f);
            h1 = make_float4(0.f, 0.f, 0.f, 0.f);
        }
        uint32_t* Ah = As + buf * 2560 + lrow * 20;
        const int w = lf4 * 2;
        Ah[w]     = pk_hi(h0.x, h0.y);
        Ah[w + 1] = pk_hi(h0.z, h0.w);
        Ah[w + 8] = pk_hi(h1.x, h1.y);
        Ah[w + 9] = pk_hi(h1.z, h1.w);
    };
    auto stageB = [&](int buf, int k0) {
        const int gr0 = k0 >> 2;
#pragma unroll
        for (int i = 0; i < 4; i++) {
            int f = t + i * 512;
            int plane = f >> 10, g = f & 1023;
            int rl = g >> 7, c4 = (g & 127) * 4;
            cpa16(&Bs[buf * 8320 + plane * 4160 + rl * 520 + c4],
                  W2p + plane * PK2 + (long)(gr0 + rl) * 1024 + n0blk * 2 + c4);
        }
        cp_commit();
    };

    float c[2][8][4];
#pragma unroll
    for (int mt = 0; mt < 2; mt++)
#pragma unroll
        for (int nt = 0; nt < 8; nt++)
#pragma unroll
            for (int e = 0; e < 4; e++) c[mt][nt][e] = 0.f;

    ldgA(0); stageB(0, 0); stsA(0, 0);
    int buf = 0;
    for (int k0 = 0; k0 < REP; k0 += 32) {
        const bool more = (k0 + 32 < REP);
        cp_wait<0>();
        __syncthreads();
        if (more) { ldgA(k0 + 32); stageB(buf ^ 1, k0 + 32); }

        const uint32_t* Ah = As + buf * 2560;
        const uint32_t* Bh = Bs + buf * 8320;
        const uint32_t* Bl = Bh + 4160;
#pragma unroll
        for (int k16 = 0; k16 < 2; k16++) {
            const int kb = k16 * 8;
            uint32_t ah[2][4];
#pragma unroll
            for (int mt = 0; mt < 2; mt++) {
                int r0 = (m0 + mt * 16 + gid) * 20;
                int r1 = r0 + 160;
                ah[mt][0] = Ah[r0 + kb + tig];
                ah[mt][1] = Ah[r1 + kb + tig];
                ah[mt][2] = Ah[r0 + kb + tig + 4];
                ah[mt][3] = Ah[r1 + kb + tig + 4];
            }
            const int brow = (k16 * 4 + tig) * 520;
#pragma unroll
            for (int nt = 0; nt < 8; nt++) {
                int cw = brow + 2 * (n0w + nt * 8 + gid);
                uint2 b2h = *(const uint2*)&Bh[cw];
                uint2 b2l = *(const uint2*)&Bl[cw];
                uint32_t bh[2] = { b2h.x, b2h.y };
                uint32_t bl[2] = { b2l.x, b2l.y };
#pragma unroll
                for (int mt = 0; mt < 2; mt++) {
                    mma16(c[mt][nt], ah[mt], bh);
                    mma16(c[mt][nt], ah[mt], bl);
                }
            }
        }
        if (more) stsA(buf ^ 1, k0 + 32);
        buf ^= 1;
    }

    float rp[4] = { 0.f, 0.f, 0.f, 0.f };
#pragma unroll
    for (int mt = 0; mt < 2; mt++) {
#pragma unroll
        for (int nt = 0; nt < 8; nt++) {
            int col = n0blk + n0w + nt * 8 + 2 * tig;
            float b2a = b2[col], b2b = b2[col + 1];
            float w3a = W3[col], w3b = W3[col + 1];
            rp[2 * mt + 0] += fmaxf(c[mt][nt][0] + b2a, 0.f) * w3a
                            + fmaxf(c[mt][nt][1] + b2b, 0.f) * w3b;
            rp[2 * mt + 1] += fmaxf(c[mt][nt][2] + b2a, 0.f) * w3a
                            + fmaxf(c[mt][nt][3] + b2b, 0.f) * w3b;
        }
    }
#pragma unroll
    for (int e = 0; e < 4; e++) {
        float v = rp[e];
        v += __shfl_xor_sync(0xffffffffu, v, 1);
        v += __shfl_xor_sync(0xffffffffu, v, 2);
        int mt = e >> 1, o = e & 1;
        if (tig == 0) wpart[(m0 + mt * 16 + o * 8 + gid) * 4 + wn] = v;
    }
    __syncthreads();
    if (t < 128) {
        float s = wpart[t * 4 + 0] + wpart[t * 4 + 1]
                + wpart[t * 4 + 2] + wpart[t * 4 + 3];
        wsum[(long)nblk * (BB * 1024) + bi * 1024 + mblk * 128 + t] = s;
    }
}

// ---------------- sigmoid over summed W3 partials ------------------------------
__global__ __launch_bounds__(1024) void sigmoid_k(
    const float* __restrict__ wsum, const float* __restrict__ b3,
    float* __restrict__ Aout)
{
    const int bi = blockIdx.x, m = threadIdx.x;
    if (m < MM) {
        float s = wsum[bi * 1024 + m] + wsum[BB * 1024 + bi * 1024 + m] + b3[0];
        int x = m / 63; int r = m - 63 * x; int y = r + (r >= x ? 1 : 0);
        Aout[(bi * 16 + x) * 64 + y] = 1.f / (1.f + expf(-s));
    }
}

// ---------------- msg_h = A @ O ------------------------------------------------
__global__ __launch_bounds__(256) void msg_h_k(
    const float* __restrict__ Ag, const float* __restrict__ O, float* __restrict__ mh)
{
    __shared__ float As[NH * NN];
    const int b = blockIdx.y, t = threadIdx.x;
#pragma unroll
    for (int i = 0; i < 4; i++) As[t + 256 * i] = Ag[b * NH * NN + t + 256 * i];
    __syncthreads();
    const int j = blockIdx.x * 256 + t;
    float acc[NH];
#pragma unroll
    for (int x = 0; x < NH; x++) acc[x] = 0.f;
    for (int n = 0; n < NN; n++) {
        float o = O[((long)(b * NN + n)) * 1024 + j];
#pragma unroll
        for (int x = 0; x < NH; x++) acc[x] += As[x * NN + n] * o;
    }
#pragma unroll
    for (int x = 0; x < NH; x++) mh[((long)(b * NH + x)) * 1024 + j] = acc[x];
}

// ---------------- msg_o = A^T @ S ----------------------------------------------
__global__ __launch_bounds__(256) void msg_o_k(
    const float* __restrict__ Ag, const float* __restrict__ Sm, float* __restrict__ mo)
{
    __shared__ float As[NH * NN];
    const int b = blockIdx.y, t = threadIdx.x;
#pragma unroll
    for (int i = 0; i < 4; i++) As[t + 256 * i] = Ag[b * NH * NN + t + 256 * i];
    __syncthreads();
    const int j = blockIdx.x * 256 + t;
    float s[NH];
#pragma unroll
    for (int x = 0; x < NH; x++) s[x] = Sm[((long)(b * NH + x)) * 1024 + j];
    for (int n = 0; n < NN; n++) {
        float acc = 0.f;
#pragma unroll
        for (int x = 0; x < NH; x++) acc += As[x * NN + n] * s[x];
        mo[((long)(b * NN + n)) * 1024 + j] = acc;
    }
}

// ---------------- output assembly (split) --------------------------------------
__device__ __forceinline__ float lis_f(float s) {
    return 8.3f / (1.f + expf(12.f - 10.f * s));
}

// pair gather (depends on final enc)
__global__ __launch_bounds__(128) void out_pair_k(
    const float* __restrict__ enc, float* __restrict__ out)
{
    const int b = blockIdx.y, m = blockIdx.x, t = threadIdx.x;
    const int x = m / 63; const int r = m - 63 * x; const int y = r + (r >= x ? 1 : 0);
    const long row = (long)b * MM + m;

    const float4* ex = (const float4*)(enc + ((long)(b * NN + x)) * RR);
    const float4* ey = (const float4*)(enc + ((long)(b * NN + y)) * RR);
    float4* po = (float4*)(out + row * 2048);
#pragma unroll
    for (int i = 0; i < 4; i++) {
        int q = t + (i << 7);
        po[q] = (q < 256) ? ex[q] : ey[q - 256];
    }
}

// coords + prior (depends only on final Ag + inputs -> overlaps tail chain)
__global__ __launch_bounds__(128) void out_meta_k(
    const float* __restrict__ Ag, const float* __restrict__ coords,
    const int* __restrict__ labels, const float* __restrict__ scores,
    float* __restrict__ out)
{
    const int b = blockIdx.y, m = blockIdx.x, t = threadIdx.x;
    const int x = m / 63; const int r = m - 63 * x; const int y = r + (r >= x ? 1 : 0);
    const long row = (long)b * MM + m;

    if (t < 4)        out[OFF_BH + row * 4 + t]       = coords[(b * NN + x) * 4 + t];
    else if (t < 8)   out[OFF_BO + row * 4 + (t - 4)] = coords[(b * NN + y) * 4 + (t - 4)];

    const int lbl = labels[b * NN + y];
    const float val = Ag[(b * NH + x) * NN + y] *
                      lis_f(scores[b * NN + x]) * lis_f(scores[b * NN + y]);
    for (int c = t; c < NCLS; c += 128)
        out[OFF_PR + row * (long)NCLS + c] = (c == lbl) ? val : 0.f;
}

// ---------------- host orchestration -------------------------------------------
extern "C" void kernel_launch(void* const* d_in, const int* in_sizes, int n_in,
                              void* d_out, int out_size)
{
    const float* box_features = (const float*)d_in[0];
    const float* box_coords   = (const float*)d_in[1];
    const int*   box_labels   = (const int*)  d_in[2];
    const float* box_scores   = (const float*)d_in[3];
    const float* W1  = (const float*)d_in[4];
    const float* b1  = (const float*)d_in[5];
    const float* W2  = (const float*)d_in[6];
    const float* b2  = (const float*)d_in[7];
    const float* W3  = (const float*)d_in[8];
    const float* b3  = (const float*)d_in[9];
    const float* Ws  = (const float*)d_in[10];
    const float* bs  = (const float*)d_in[11];
    const float* Wo  = (const float*)d_in[12];
    const float* bo  = (const float*)d_in[13];
    const float* Wsu = (const float*)d_in[14];
    const float* Wou = (const float*)d_in[15];
    float* out = (float*)d_out;

    float *encA, *encB, *UV, *O, *mh, *eh, *Sb, *mo, *Ag, *wsum;
    uint32_t *W1p, *W2p, *Wop, *Wsp, *Wsup, *Woup;
    cudaGetSymbolAddress((void**)&encA, g_encA);
    cudaGetSymbolAddress((void**)&encB, g_encB);
    cudaGetSymbolAddress((void**)&UV,   g_UV);
    cudaGetSymbolAddress((void**)&O,    g_O);
    cudaGetSymbolAddress((void**)&mh,   g_mh);
    cudaGetSymbolAddress((void**)&eh,   g_eh);
    cudaGetSymbolAddress((void**)&Sb,   g_S);
    cudaGetSymbolAddress((void**)&mo,   g_mo);
    cudaGetSymbolAddress((void**)&Ag,   g_A);
    cudaGetSymbolAddress((void**)&wsum, g_wsum);
    cudaGetSymbolAddress((void**)&W1p,  g_W1p);
    cudaGetSymbolAddress((void**)&W2p,  g_W2p);
    cudaGetSymbolAddress((void**)&Wop,  g_Wop);
    cudaGetSymbolAddress((void**)&Wsp,  g_Wsp);
    cudaGetSymbolAddress((void**)&Wsup, g_Wsup);
    cudaGetSymbolAddress((void**)&Woup, g_Woup);

    cudaFuncSetAttribute(gemm_f16p,
                         cudaFuncAttributeMaxDynamicSharedMemorySize, GEMM_SMEM);
    cudaFuncSetAttribute(pair_mlp_mma,
                         cudaFuncAttributeMaxDynamicSharedMemorySize, PAIR_SMEM);

    // aux stream + events (created per call; never destroyed during capture)
    cudaStream_t s1;
    cudaStreamCreateWithFlags(&s1, cudaStreamNonBlocking);
    cudaEvent_t ev[8];
    for (int i = 0; i < 8; i++)
        cudaEventCreateWithFlags(&ev[i], cudaEventDisableTiming);

    // ---- prepack, split across streams ----
    cudaEventRecord(ev[0], 0);
    cudaStreamWaitEvent(s1, ev[0], 0);
    pack_wuv<<<512, 256>>>(W1, W1p);
    pack_w<<<256, 256>>>(Wo,  Wop,  512, 1024);
    pack_w<<<512, 256>>>(Wsu, Wsup, 1024, 1024);
    pack_w<<<256, 256, 0, s1>>>(W2, W2p, 512, 512);
    pack_w<<<256, 256, 0, s1>>>(Ws, Wsp, 512, 1024);
    pack_w<<<512, 256, 0, s1>>>(Wou, Woup, 1024, 1024);
    cudaMemcpyAsync(encA, box_features, (size_t)BB * NN * RR * 4,
                    cudaMemcpyDeviceToDevice, s1);
    cudaEventRecord(ev[1], s1);
    cudaStreamWaitEvent(0, ev[1], 0);

    const long sEnc = (long)NN * RR;   // 65536
    const long sH   = (long)NH * RR;   // 16384
    const float* NUL = (const float*)0;

    for (int it = 0; it < 2; it++) {
        float* encIn  = (it == 0) ? encA : encB;
        float* encOut = (it == 0) ? encB : encA;
        cudaEvent_t evF = ev[2 + 2 * it], evJ = ev[3 + 2 * it];

        // fork: O gemm on s1 (depends only on encIn)
        cudaEventRecord(evF, 0);
        cudaStreamWaitEvent(s1, evF, 0);
        gemm_f16p<<<dim3(8, 32), 256, GEMM_SMEM, s1>>>(
            encIn, NUL, 6, sEnc, 1024, NUL, 0,
            Wop, bo, O, 1024, 512L * 1024, 1024, 1024, 1);

        // s0: UV gemm -> pair MLP -> sigmoid
        gemm_f16p<<<dim3(16, 32), 256, GEMM_SMEM>>>(
            encIn, NUL, 6, sEnc, 1024, NUL, 0,
            W1p, NUL, UV, 2048, 512L * 2048, 2048, 1024, 0);
        pair_mlp_mma<<<dim3(8, 2, BB), 512, PAIR_SMEM>>>(
            UV, b1, W2p, b2, W3, wsum);
        sigmoid_k<<<BB, 1024>>>(wsum, b3, Ag);

        // iter 2: coords+prior depend only on final Ag -> overlap on s1
        if (it == 1) {
            cudaEventRecord(ev[6], 0);
            cudaStreamWaitEvent(s1, ev[6], 0);
            out_meta_k<<<dim3(MM, BB), 128, 0, s1>>>(
                Ag, box_coords, box_labels, box_scores, out);
        }

        // join before msg_h (needs A and O)
        cudaEventRecord(evJ, s1);
        cudaStreamWaitEvent(0, evJ, 0);

        msg_h_k<<<dim3(4, BB), 256>>>(Ag, O, mh);
        gemm_f16p<<<dim3(8, 8), 256, GEMM_SMEM>>>(
            encIn, NUL, 4, sEnc, 1024, mh, sH,
            Wsup, NUL, eh, 1024, 1024L * 1024, 1024, 2048, 0);
        gemm_f16p<<<dim3(8, 8), 256, GEMM_SMEM>>>(
            eh, NUL, 4, sH, 1024, NUL, 0,
            Wsp, bs, Sb, 1024, 512L * 1024, 1024, 1024, 1);
        msg_o_k<<<dim3(4, BB), 256>>>(Ag, Sb, mo);
        // splice handled via A1o override: rows n<16 read eh instead of encIn
        gemm_f16p<<<dim3(8, 32), 256, GEMM_SMEM>>>(
            encIn, eh, 6, sEnc, 1024, mo, sEnc,
            Woup, NUL, encOut, 1024, 1024L * 1024, 1024, 2048, 0);
    }

    // pair gather (needs final enc)
    out_pair_k<<<dim3(MM, BB), 128>>>(encA, out);

    // final join: make s0 wait for s1's out_meta before capture ends
    cudaEventRecord(ev[7], s1);
    cudaStreamWaitEvent(0, ev[7], 0);
    (void)in_sizes; (void)n_in; (void)out_size;
}

// round 16
// speedup vs baseline: 1.1342x; 1.0456x over previous
#include <cuda_runtime.h>
#include <cuda_fp16.h>
#include <math.h>
#include <stdint.h>

// Problem constants
#define BB   32
#define NN   64
#define NH   16
#define RR   1024
#define REP  1024
#define MM   1008
#define NCLS 117

// Output layout offsets (floats)
#define OFF_BH  66060288L
#define OFF_BO  66189312L
#define OFF_PR  66318336L

// ---------------- scratch (device globals) -----------------------------------
__device__ float g_encA[BB * NN * RR];
__device__ float g_encB[BB * NN * RR];
__device__ float g_UV [BB * NN * 2048];
__device__ float g_O  [BB * NN * REP];
__device__ float g_mh [BB * NH * REP];
__device__ float g_eh [BB * NH * RR];
__device__ float g_S  [BB * NH * REP];
__device__ float g_mo [BB * NN * REP];
__device__ float g_A  [BB * NH * NN];
__device__ float g_wsum[2 * BB * 1024];   // per-n-block partial W3 sums

// packed weights, interleaved-pair layout, fp16 hi/lo planes
__device__ uint32_t g_W1p [1024L * 2048];
__device__ uint32_t g_W2p [1024L * 512];
__device__ uint32_t g_Wop [1024L * 1024];
__device__ uint32_t g_Wsp [1024L * 1024];
__device__ uint32_t g_Wsup[2048L * 1024];
__device__ uint32_t g_Woup[2048L * 1024];

// ---------------- helpers ----------------------------------------------------
__device__ __forceinline__ void mma16(float* c, const uint32_t* a, const uint32_t* b)
{
    asm volatile(
        "mma.sync.aligned.m16n8k16.row.col.f32.f16.f16.f32 "
        "{%0,%1,%2,%3}, {%4,%5,%6,%7}, {%8,%9}, {%0,%1,%2,%3};\n"
        : "+f"(c[0]), "+f"(c[1]), "+f"(c[2]), "+f"(c[3])
        : "r"(a[0]), "r"(a[1]), "r"(a[2]), "r"(a[3]), "r"(b[0]), "r"(b[1]));
}

__device__ __forceinline__ uint32_t pk_hi(float x0, float x1)
{
    uint32_t r;
    asm("cvt.rn.f16x2.f32 %0, %1, %2;" : "=r"(r) : "f"(x1), "f"(x0));
    return r;
}
__device__ __forceinline__ uint32_t pk_lo(float x0, float x1, uint32_t hi)
{
    __half2 h = *reinterpret_cast<__half2*>(&hi);
    float l0 = x0 - __low2float(h);
    float l1 = x1 - __high2float(h);
    return pk_hi(l0, l1);
}

__device__ __forceinline__ void cpa16(void* smem, const void* gmem)
{
    uint32_t s = (uint32_t)__cvta_generic_to_shared(smem);
    asm volatile("cp.async.cg.shared.global [%0], [%1], 16;\n" :: "r"(s), "l"(gmem));
}
__device__ __forceinline__ void cp_commit()
{
    asm volatile("cp.async.commit_group;\n");
}
template <int N> __device__ __forceinline__ void cp_wait()
{
    asm volatile("cp.async.wait_group %0;\n" :: "n"(N));
}

// ---------------- weight prepack (interleaved-pair layout, fp16 planes) -------
__global__ __launch_bounds__(256) void pack_w(
    const float* __restrict__ W, uint32_t* __restrict__ Wp, int Kh, int N)
{
    const long plane = (long)Kh * N;
    const long total = 2 * plane;
    const int rowlen = 2 * N;
    for (long i = blockIdx.x * blockDim.x + threadIdx.x; i < total;
         i += (long)gridDim.x * blockDim.x) {
        int p = (int)(i / plane);
        long rem = i - (long)p * plane;
        int row = (int)(rem / rowlen);
        int col2 = (int)(rem - (long)row * rowlen);
        int n = col2 >> 1, j = col2 & 1;
        int q = row >> 2, tig = row & 3;
        int kp = q * 8 + tig + 4 * j;
        float x0 = W[(long)(2 * kp) * N + n];
        float x1 = W[(long)(2 * kp + 1) * N + n];
        uint32_t hi = pk_hi(x0, x1);
        Wp[i] = p ? pk_lo(x0, x1, hi) : hi;
    }
}

// fused UV pack: Wuv(k, c) = c<1024 ? W1[k][c] : W1[1024+k][c-1024]
__global__ __launch_bounds__(256) void pack_wuv(
    const float* __restrict__ W1, uint32_t* __restrict__ Wp)
{
    const long plane = 512L * 2048;
    const long total = 2 * plane;
    for (long i = blockIdx.x * blockDim.x + threadIdx.x; i < total;
         i += (long)gridDim.x * blockDim.x) {
        int p = (int)(i / plane);
        long rem = i - (long)p * plane;
        int row = (int)(rem >> 12);
        int col2 = (int)(rem & 4095);
        int n = col2 >> 1, j = col2 & 1;
        int q = row >> 2, tig = row & 3;
        int kp = q * 8 + tig + 4 * j;
        int k0 = 2 * kp, k1 = 2 * kp + 1;
        float x0, x1;
        if (n < 1024) {
            x0 = W1[(long)k0 * 1024 + n];
            x1 = W1[(long)k1 * 1024 + n];
        } else {
            x0 = W1[(long)(1024 + k0) * 1024 + (n - 1024)];
            x1 = W1[(long)(1024 + k1) * 1024 + (n - 1024)];
        }
        uint32_t hi = pk_hi(x0, x1);
        Wp[i] = p ? pk_lo(x0, x1, hi) : hi;
    }
}

// ---------------- batched GEMM (fp16 2-product, BM=64 x BN=128) ---------------
// R13 winner configuration. 256 threads, 2 blocks/SM.
#define GEMM_SMEM ((2560 + 8448) * 4)
__global__ __launch_bounds__(256, 2) void gemm_f16p(
    const float* __restrict__ A1, const float* __restrict__ A1o,
    int lrpb, long sA1, int K1,
    const float* __restrict__ A2, long sA2,
    const uint32_t* __restrict__ Wp, const float* __restrict__ bias,
    float* __restrict__ C, int Nw, long PKw, int ldc, int Ktot, int do_relu)
{
    extern __shared__ __align__(16) uint32_t sm[];
    uint32_t* As = sm;
    uint32_t* Bs = sm + 2560;

    const int t = threadIdx.x, lane = t & 31, warp = t >> 5;
    const int gid = lane >> 2, tig = lane & 3;
    const int wm = warp >> 2, wn = warp & 3;
    const int m0 = wm * 32, n0w = wn * 32;
    const long bn0 = (long)blockIdx.x * 128;
    const int bm0 = blockIdx.y * 64;
    const int K2 = Ktot - K1;
    const int rmask = (1 << lrpb) - 1;

    const int lrow = t >> 2, lf4 = t & 3;
    const int grow = bm0 + lrow;
    const int b = grow >> lrpb, n = grow & rmask;
    const float* p1 = (A1o && n < 16)
                        ? (A1o + (long)b * 16384 + (long)n * 1024)
                        : (A1 + (long)b * sA1 + (long)n * K1);
    const float* p2 = A2 ? (A2 + (long)b * sA2 + (long)n * K2) : p1;

    float4 ra0, ra1;
    auto ldgA = [&](int k0) {
        const float* rp = (k0 < K1) ? (p1 + k0) : (p2 + (k0 - K1));
        ra0 = *(const float4*)(rp + lf4 * 4);
        ra1 = *(const float4*)(rp + lf4 * 4 + 16);
    };
    auto stsA = [&](int buf) {
        uint32_t* Ah = As + buf * 1280 + lrow * 20;
        const int w = lf4 * 2;
        Ah[w]     = pk_hi(ra0.x, ra0.y);
        Ah[w + 1] = pk_hi(ra0.z, ra0.w);
        Ah[w + 8] = pk_hi(ra1.x, ra1.y);
        Ah[w + 9] = pk_hi(ra1.z, ra1.w);
    };
    auto stageB = [&](int buf, int k0) {
        const int gr0 = k0 >> 2;
#pragma unroll
        for (int i = 0; i < 4; i++) {
            int f = t + i * 256;
            int plane = f >> 9, g = f & 511;
            int rl = g >> 6, c4 = (g & 63) * 4;
            cpa16(&Bs[buf * 4224 + plane * 2112 + rl * 264 + c4],
                  Wp + plane * PKw + (long)(gr0 + rl) * (2 * Nw) + bn0 * 2 + c4);
        }
        cp_commit();
    };

    float c[2][4][4];
#pragma unroll
    for (int mt = 0; mt < 2; mt++)
#pragma unroll
        for (int nt = 0; nt < 4; nt++)
#pragma unroll
            for (int e = 0; e < 4; e++) c[mt][nt][e] = 0.f;

    ldgA(0); stageB(0, 0); stsA(0);
    int buf = 0;
    for (int k0 = 0; k0 < Ktot; k0 += 32) {
        const bool more = (k0 + 32 < Ktot);
        cp_wait<0>();
        __syncthreads();
        if (more) { ldgA(k0 + 32); stageB(buf ^ 1, k0 + 32); }

        const uint32_t* Ah = As + buf * 1280;
        const uint32_t* Bh = Bs + buf * 4224;
        const uint32_t* Bl = Bh + 2112;
#pragma unroll
        for (int k16 = 0; k16 < 2; k16++) {
            const int kb = k16 * 8;
            uint32_t ah[2][4];
#pragma unroll
            for (int mt = 0; mt < 2; mt++) {
                int r0 = (m0 + mt * 16 + gid) * 20;
                int r1 = r0 + 160;
                ah[mt][0] = Ah[r0 + kb + tig];
                ah[mt][1] = Ah[r1 + kb + tig];
                ah[mt][2] = Ah[r0 + kb + tig + 4];
                ah[mt][3] = Ah[r1 + kb + tig + 4];
            }
            const int brow = (k16 * 4 + tig) * 264;
#pragma unroll
            for (int nt = 0; nt < 4; nt++) {
                int cw = brow + 2 * (n0w + nt * 8 + gid);
                uint2 b2h = *(const uint2*)&Bh[cw];
                uint2 b2l = *(const uint2*)&Bl[cw];
                uint32_t bh[2] = { b2h.x, b2h.y };
                uint32_t bl[2] = { b2l.x, b2l.y };
#pragma unroll
                for (int mt = 0; mt < 2; mt++) {
                    mma16(c[mt][nt], ah[mt], bh);
                    mma16(c[mt][nt], ah[mt], bl);
                }
            }
        }
        if (more) stsA(buf ^ 1);
        buf ^= 1;
    }

#pragma unroll
    for (int mt = 0; mt < 2; mt++) {
#pragma unroll
        for (int nt = 0; nt < 4; nt++) {
            long col = bn0 + n0w + nt * 8 + 2 * tig;
            float b0v = 0.f, b1v = 0.f;
            if (bias) { b0v = bias[col]; b1v = bias[col + 1]; }
            int r = bm0 + m0 + mt * 16 + gid;
            float v0 = c[mt][nt][0] + b0v, v1 = c[mt][nt][1] + b1v;
            float v2 = c[mt][nt][2] + b0v, v3 = c[mt][nt][3] + b1v;
            if (do_relu) {
                v0 = fmaxf(v0, 0.f); v1 = fmaxf(v1, 0.f);
                v2 = fmaxf(v2, 0.f); v3 = fmaxf(v3, 0.f);
            }
            *(float2*)&C[(long)r * ldc + col]       = make_float2(v0, v1);
            *(float2*)&C[(long)(r + 8) * ldc + col] = make_float2(v2, v3);
        }
    }
}

// ---------------- fused pair MLP (fp16 2-product, BM=128 x BN=256) ------------
// R13 winner. grid (8, 2, 32), 512 threads.
#define PAIR_SMEM ((5120 + 16640 + 512 + 1024) * 4)
__global__ __launch_bounds__(512, 1) void pair_mlp_mma(
    const float* __restrict__ UV, const float* __restrict__ b1,
    const uint32_t* __restrict__ W2p, const float* __restrict__ b2,
    const float* __restrict__ W3, float* __restrict__ wsum)
{
    extern __shared__ __align__(16) uint32_t sm[];
    uint32_t* As = sm;
    uint32_t* Bs = sm + 5120;
    float* wpart = (float*)(sm + 5120 + 16640);
    float* b1s   = (float*)(sm + 5120 + 16640 + 512);

    const int t = threadIdx.x, lane = t & 31, warp = t >> 5;
    const int gid = lane >> 2, tig = lane & 3;
    const int wm = warp >> 2, wn = warp & 3;
    const int m0 = wm * 32, n0w = wn * 64;
    const int mblk = blockIdx.x, nblk = blockIdx.y, bi = blockIdx.z;
    const int n0blk = nblk * 256;
    const long PK2 = 512L * 512;

    b1s[t] = b1[t];
    b1s[t + 512] = b1[t + 512];
    __syncthreads();

    const int lrow = t >> 2, lf4 = t & 3;
    const int mld = mblk * 128 + lrow;
    const int valid = (mld < MM);
    int xl = 0, yl = 0;
    if (valid) { xl = mld / 63; int rl = mld - 63 * xl; yl = rl + (rl >= xl ? 1 : 0); }
    const float* Urow = UV + ((long)(bi * 64 + xl)) * 2048;
    const float* Vrow = UV + ((long)(bi * 64 + yl)) * 2048 + 1024;

    float4 ru0, ru1, rv0, rv1;
    auto ldgA = [&](int k0) {
        ru0 = *(const float4*)(Urow + k0 + lf4 * 4);
        ru1 = *(const float4*)(Urow + k0 + lf4 * 4 + 16);
        rv0 = *(const float4*)(Vrow + k0 + lf4 * 4);
        rv1 = *(const float4*)(Vrow + k0 + lf4 * 4 + 16);
    };
    auto stsA = [&](int buf, int k0) {
        float4 rb0 = *(const float4*)&b1s[k0 + lf4 * 4];
        float4 rb1 = *(const float4*)&b1s[k0 + lf4 * 4 + 16];
        float4 h0, h1;
        h0.x = fmaxf(ru0.x + rv0.x + rb0.x, 0.f);
        h0.y = fmaxf(ru0.y + rv0.y + rb0.y, 0.f);
        h0.z = fmaxf(ru0.z + rv0.z + rb0.z, 0.f);
        h0.w = fmaxf(ru0.w + rv0.w + rb0.w, 0.f);
        h1.x = fmaxf(ru1.x + rv1.x + rb1.x, 0.f);
        h1.y = fmaxf(ru1.y + rv1.y + rb1.y, 0.f);
        h1.z = fmaxf(ru1.z + rv1.z + rb1.z, 0.f);
        h1.w = fmaxf(ru1.w + rv1.w + rb1.w, 0.f);
        if (!valid) {
            h0 = make_float4(0.f, 0.f, 0.f, 0.f);
            h1 = make_float4(0.f, 0.f, 0.f, 0.f);
        }
        uint32_t* Ah = As + buf * 2560 + lrow * 20;
        const int w = lf4 * 2;
        Ah[w]     = pk_hi(h0.x, h0.y);
        Ah[w + 1] = pk_hi(h0.z, h0.w);
        Ah[w + 8] = pk_hi(h1.x, h1.y);
        Ah[w + 9] = pk_hi(h1.z, h1.w);
    };
    auto stageB = [&](int buf, int k0) {
        const int gr0 = k0 >> 2;
#pragma unroll
        for (int i = 0; i < 4; i++) {
            int f = t + i * 512;
            int plane = f >> 10, g = f & 1023;
            int rl = g >> 7, c4 = (g & 127) * 4;
            cpa16(&Bs[buf * 8320 + plane * 4160 + rl * 520 + c4],
                  W2p + plane * PK2 + (long)(gr0 + rl) * 1024 + n0blk * 2 + c4);
        }
        cp_commit();
    };

    float c[2][8][4];
#pragma unroll
    for (int mt = 0; mt < 2; mt++)
#pragma unroll
        for (int nt = 0; nt < 8; nt++)
#pragma unroll
            for (int e = 0; e < 4; e++) c[mt][nt][e] = 0.f;

    ldgA(0); stageB(0, 0); stsA(0, 0);
    int buf = 0;
    for (int k0 = 0; k0 < REP; k0 += 32) {
        const bool more = (k0 + 32 < REP);
        cp_wait<0>();
        __syncthreads();
        if (more) { ldgA(k0 + 32); stageB(buf ^ 1, k0 + 32); }

        const uint32_t* Ah = As + buf * 2560;
        const uint32_t* Bh = Bs + buf * 8320;
        const uint32_t* Bl = Bh + 4160;
#pragma unroll
        for (int k16 = 0; k16 < 2; k16++) {
            const int kb = k16 * 8;
            uint32_t ah[2][4];
#pragma unroll
            for (int mt = 0; mt < 2; mt++) {
                int r0 = (m0 + mt * 16 + gid) * 20;
                int r1 = r0 + 160;
                ah[mt][0] = Ah[r0 + kb + tig];
                ah[mt][1] = Ah[r1 + kb + tig];
                ah[mt][2] = Ah[r0 + kb + tig + 4];
                ah[mt][3] = Ah[r1 + kb + tig + 4];
            }
            const int brow = (k16 * 4 + tig) * 520;
#pragma unroll
            for (int nt = 0; nt < 8; nt++) {
                int cw = brow + 2 * (n0w + nt * 8 + gid);
                uint2 b2h = *(const uint2*)&Bh[cw];
                uint2 b2l = *(const uint2*)&Bl[cw];
                uint32_t bh[2] = { b2h.x, b2h.y };
                uint32_t bl[2] = { b2l.x, b2l.y };
#pragma unroll
                for (int mt = 0; mt < 2; mt++) {
                    mma16(c[mt][nt], ah[mt], bh);
                    mma16(c[mt][nt], ah[mt], bl);
                }
            }
        }
        if (more) stsA(buf ^ 1, k0 + 32);
        buf ^= 1;
    }

    float rp[4] = { 0.f, 0.f, 0.f, 0.f };
#pragma unroll
    for (int mt = 0; mt < 2; mt++) {
#pragma unroll
        for (int nt = 0; nt < 8; nt++) {
            int col = n0blk + n0w + nt * 8 + 2 * tig;
            float b2a = b2[col], b2b = b2[col + 1];
            float w3a = W3[col], w3b = W3[col + 1];
            rp[2 * mt + 0] += fmaxf(c[mt][nt][0] + b2a, 0.f) * w3a
                            + fmaxf(c[mt][nt][1] + b2b, 0.f) * w3b;
            rp[2 * mt + 1] += fmaxf(c[mt][nt][2] + b2a, 0.f) * w3a
                            + fmaxf(c[mt][nt][3] + b2b, 0.f) * w3b;
        }
    }
#pragma unroll
    for (int e = 0; e < 4; e++) {
        float v = rp[e];
        v += __shfl_xor_sync(0xffffffffu, v, 1);
        v += __shfl_xor_sync(0xffffffffu, v, 2);
        int mt = e >> 1, o = e & 1;
        if (tig == 0) wpart[(m0 + mt * 16 + o * 8 + gid) * 4 + wn] = v;
    }
    __syncthreads();
    if (t < 128) {
        float s = wpart[t * 4 + 0] + wpart[t * 4 + 1]
                + wpart[t * 4 + 2] + wpart[t * 4 + 3];
        wsum[(long)nblk * (BB * 1024) + bi * 1024 + mblk * 128 + t] = s;
    }
}

// ---------------- sigmoid over summed W3 partials ------------------------------
__global__ __launch_bounds__(1024) void sigmoid_k(
    const float* __restrict__ wsum, const float* __restrict__ b3,
    float* __restrict__ Aout)
{
    const int bi = blockIdx.x, m = threadIdx.x;
    if (m < MM) {
        float s = wsum[bi * 1024 + m] + wsum[BB * 1024 + bi * 1024 + m] + b3[0];
        int x = m / 63; int r = m - 63 * x; int y = r + (r >= x ? 1 : 0);
        Aout[(bi * 16 + x) * 64 + y] = 1.f / (1.f + expf(-s));
    }
}

// ---------------- msg_h = A @ O ------------------------------------------------
__global__ __launch_bounds__(256) void msg_h_k(
    const float* __restrict__ Ag, const float* __restrict__ O, float* __restrict__ mh)
{
    __shared__ float As[NH * NN];
    const int b = blockIdx.y, t = threadIdx.x;
#pragma unroll
    for (int i = 0; i < 4; i++) As[t + 256 * i] = Ag[b * NH * NN + t + 256 * i];
    __syncthreads();
    const int j = blockIdx.x * 256 + t;
    float acc[NH];
#pragma unroll
    for (int x = 0; x < NH; x++) acc[x] = 0.f;
    for (int n = 0; n < NN; n++) {
        float o = O[((long)(b * NN + n)) * 1024 + j];
#pragma unroll
        for (int x = 0; x < NH; x++) acc[x] += As[x * NN + n] * o;
    }
#pragma unroll
    for (int x = 0; x < NH; x++) mh[((long)(b * NH + x)) * 1024 + j] = acc[x];
}

// ---------------- msg_o = A^T @ S ----------------------------------------------
__global__ __launch_bounds__(256) void msg_o_k(
    const float* __restrict__ Ag, const float* __restrict__ Sm, float* __restrict__ mo)
{
    __shared__ float As[NH * NN];
    const int b = blockIdx.y, t = threadIdx.x;
#pragma unroll
    for (int i = 0; i < 4; i++) As[t + 256 * i] = Ag[b * NH * NN + t + 256 * i];
    __syncthreads();
    const int j = blockIdx.x * 256 + t;
    float s[NH];
#pragma unroll
    for (int x = 0; x < NH; x++) s[x] = Sm[((long)(b * NH + x)) * 1024 + j];
    for (int n = 0; n < NN; n++) {
        float acc = 0.f;
#pragma unroll
        for (int x = 0; x < NH; x++) acc += As[x * NN + n] * s[x];
        mo[((long)(b * NN + n)) * 1024 + j] = acc;
    }
}

// ---------------- output assembly ----------------------------------------------
__device__ __forceinline__ float lis_f(float s) {
    return 8.3f / (1.f + expf(12.f - 10.f * s));
}

__global__ __launch_bounds__(128) void out_kernel(
    const float* __restrict__ enc, const float* __restrict__ Ag,
    const float* __restrict__ coords, const int* __restrict__ labels,
    const float* __restrict__ scores, float* __restrict__ out)
{
    const int b = blockIdx.y, m = blockIdx.x, t = threadIdx.x;
    const int x = m / 63; const int r = m - 63 * x; const int y = r + (r >= x ? 1 : 0);
    const long row = (long)b * MM + m;

    const float4* ex = (const float4*)(enc + ((long)(b * NN + x)) * RR);
    const float4* ey = (const float4*)(enc + ((long)(b * NN + y)) * RR);
    float4* po = (float4*)(out + row * 2048);
#pragma unroll
    for (int i = 0; i < 4; i++) {
        int q = t + (i << 7);
        po[q] = (q < 256) ? ex[q] : ey[q - 256];
    }
    if (t < 4)        out[OFF_BH + row * 4 + t]       = coords[(b * NN + x) * 4 + t];
    else if (t < 8)   out[OFF_BO + row * 4 + (t - 4)] = coords[(b * NN + y) * 4 + (t - 4)];

    const int lbl = labels[b * NN + y];
    const float val = Ag[(b * NH + x) * NN + y] *
                      lis_f(scores[b * NN + x]) * lis_f(scores[b * NN + y]);
    for (int c = t; c < NCLS; c += 128)
        out[OFF_PR + row * (long)NCLS + c] = (c == lbl) ? val : 0.f;
}

// ---------------- host orchestration -------------------------------------------
extern "C" void kernel_launch(void* const* d_in, const int* in_sizes, int n_in,
                              void* d_out, int out_size)
{
    const float* box_features = (const float*)d_in[0];
    const float* box_coords   = (const float*)d_in[1];
    const int*   box_labels   = (const int*)  d_in[2];
    const float* box_scores   = (const float*)d_in[3];
    const float* W1  = (const float*)d_in[4];
    const float* b1  = (const float*)d_in[5];
    const float* W2  = (const float*)d_in[6];
    const float* b2  = (const float*)d_in[7];
    const float* W3  = (const float*)d_in[8];
    const float* b3  = (const float*)d_in[9];
    const float* Ws  = (const float*)d_in[10];
    const float* bs  = (const float*)d_in[11];
    const float* Wo  = (const float*)d_in[12];
    const float* bo  = (const float*)d_in[13];
    const float* Wsu = (const float*)d_in[14];
    const float* Wou = (const float*)d_in[15];
    float* out = (float*)d_out;

    float *encA, *encB, *UV, *O, *mh, *eh, *Sb, *mo, *Ag, *wsum;
    uint32_t *W1p, *W2p, *Wop, *Wsp, *Wsup, *Woup;
    cudaGetSymbolAddress((void**)&encA, g_encA);
    cudaGetSymbolAddress((void**)&encB, g_encB);
    cudaGetSymbolAddress((void**)&UV,   g_UV);
    cudaGetSymbolAddress((void**)&O,    g_O);
    cudaGetSymbolAddress((void**)&mh,   g_mh);
    cudaGetSymbolAddress((void**)&eh,   g_eh);
    cudaGetSymbolAddress((void**)&Sb,   g_S);
    cudaGetSymbolAddress((void**)&mo,   g_mo);
    cudaGetSymbolAddress((void**)&Ag,   g_A);
    cudaGetSymbolAddress((void**)&wsum, g_wsum);
    cudaGetSymbolAddress((void**)&W1p,  g_W1p);
    cudaGetSymbolAddress((void**)&W2p,  g_W2p);
    cudaGetSymbolAddress((void**)&Wop,  g_Wop);
    cudaGetSymbolAddress((void**)&Wsp,  g_Wsp);
    cudaGetSymbolAddress((void**)&Wsup, g_Wsup);
    cudaGetSymbolAddress((void**)&Woup, g_Woup);

    cudaFuncSetAttribute(gemm_f16p,
                         cudaFuncAttributeMaxDynamicSharedMemorySize, GEMM_SMEM);
    cudaFuncSetAttribute(pair_mlp_mma,
                         cudaFuncAttributeMaxDynamicSharedMemorySize, PAIR_SMEM);

    // aux stream + events (created per call; never destroyed during capture)
    cudaStream_t s1;
    cudaStreamCreateWithFlags(&s1, cudaStreamNonBlocking);
    cudaEvent_t ev[8];
    for (int i = 0; i < 8; i++)
        cudaEventCreateWithFlags(&ev[i], cudaEventDisableTiming);

    // ---- startup: only W1p/W2p/Wop are needed early; defer the rest to s1 ----
    // s0: encA copy + fused-UV pack (critical path start)
    cudaEventRecord(ev[0], 0);
    cudaStreamWaitEvent(s1, ev[0], 0);
    cudaMemcpyAsync(encA, box_features, (size_t)BB * NN * RR * 4,
                    cudaMemcpyDeviceToDevice, 0);
    pack_wuv<<<512, 256>>>(W1, W1p);
    // s1: W2 pack (pair dependency), then Wo pack (O gemm dependency)
    pack_w<<<256, 256, 0, s1>>>(W2, W2p, 512, 512);
    cudaEventRecord(ev[1], s1);          // W2p ready
    pack_w<<<256, 256, 0, s1>>>(Wo, Wop, 512, 1024);

    const long sEnc = (long)NN * RR;   // 65536
    const long sH   = (long)NH * RR;   // 16384
    const float* NUL = (const float*)0;

    for (int it = 0; it < 2; it++) {
        float* encIn  = (it == 0) ? encA : encB;
        float* encOut = (it == 0) ? encB : encA;
        cudaEvent_t evF = ev[2 + 2 * it], evJ = ev[3 + 2 * it];

        // fork: O gemm on s1 (depends only on encIn; s0's encA copy ordered
        // via evF which is recorded after the copy on s0)
        cudaEventRecord(evF, 0);
        cudaStreamWaitEvent(s1, evF, 0);
        gemm_f16p<<<dim3(8, 32), 256, GEMM_SMEM, s1>>>(
            encIn, NUL, 6, sEnc, 1024, NUL, 0,
            Wop, bo, O, 1024, 512L * 1024, 1024, 1024, 1);

        // iter 0: deferred packs on s1 — hidden behind the pair MLP on s0;
        // completion ordered before the tail via evJ.
        if (it == 0) {
            pack_w<<<512, 256, 0, s1>>>(Wsu, Wsup, 1024, 1024);
            pack_w<<<256, 256, 0, s1>>>(Ws, Wsp, 512, 1024);
            pack_w<<<512, 256, 0, s1>>>(Wou, Woup, 1024, 1024);
        }

        // s0: UV gemm -> pair MLP -> sigmoid
        gemm_f16p<<<dim3(16, 32), 256, GEMM_SMEM>>>(
            encIn, NUL, 6, sEnc, 1024, NUL, 0,
            W1p, NUL, UV, 2048, 512L * 2048, 2048, 1024, 0);
        if (it == 0) cudaStreamWaitEvent(0, ev[1], 0);   // W2p ready
        pair_mlp_mma<<<dim3(8, 2, BB), 512, PAIR_SMEM>>>(
            UV, b1, W2p, b2, W3, wsum);
        sigmoid_k<<<BB, 1024>>>(wsum, b3, Ag);

        // join before msg_h (needs A and O; also orders deferred packs)
        cudaEventRecord(evJ, s1);
        cudaStreamWaitEvent(0, evJ, 0);

        msg_h_k<<<dim3(4, BB), 256>>>(Ag, O, mh);
        gemm_f16p<<<dim3(8, 8), 256, GEMM_SMEM>>>(
            encIn, NUL, 4, sEnc, 1024, mh, sH,
            Wsup, NUL, eh, 1024, 1024L * 1024, 1024, 2048, 0);
        gemm_f16p<<<dim3(8, 8), 256, GEMM_SMEM>>>(
            eh, NUL, 4, sH, 1024, NUL, 0,
            Wsp, bs, Sb, 1024, 512L * 1024, 1024, 1024, 1);
        msg_o_k<<<dim3(4, BB), 256>>>(Ag, Sb, mo);
        // splice handled via A1o override: rows n<16 read eh instead of encIn
        gemm_f16p<<<dim3(8, 32), 256, GEMM_SMEM>>>(
            encIn, eh, 6, sEnc, 1024, mo, sEnc,
            Woup, NUL, encOut, 1024, 1024L * 1024, 1024, 2048, 0);
    }

    out_kernel<<<dim3(MM, BB), 128>>>(encA, Ag, box_coords, box_labels,
                                      box_scores, out);
    (void)in_sizes; (void)n_in; (void)out_size;
}

// round 17
// speedup vs baseline: 1.1547x; 1.0181x over previous
#include <cuda_runtime.h>
#include <cuda_fp16.h>
#include <math.h>
#include <stdint.h>

// Problem constants
#define BB   32
#define NN   64
#define NH   16
#define RR   1024
#define REP  1024
#define MM   1008
#define NCLS 117

// Output layout offsets (floats)
#define OFF_BH  66060288L
#define OFF_BO  66189312L
#define OFF_PR  66318336L

// ---------------- scratch (device globals) -----------------------------------
__device__ float g_encA[BB * NN * RR];
__device__ float g_encB[BB * NN * RR];
__device__ float g_UV [BB * NN * 2048];
__device__ float g_O  [BB * NN * REP];
__device__ float g_mh [BB * NH * REP];
__device__ float g_eh [BB * NH * RR];
__device__ float g_S  [BB * NH * REP];
__device__ float g_mo [BB * NN * REP];
__device__ float g_A  [BB * NH * NN];
__device__ float g_wsum[2 * BB * 1024];   // per-n-block partial W3 sums

// packed weights, interleaved-pair layout, fp16 hi/lo planes
__device__ uint32_t g_W1p [1024L * 2048];
__device__ uint32_t g_W2p [1024L * 512];
__device__ uint32_t g_Wop [1024L * 1024];
__device__ uint32_t g_Wsp [1024L * 1024];
__device__ uint32_t g_Wsup[2048L * 1024];
__device__ uint32_t g_Woup[2048L * 1024];

// ---------------- helpers ----------------------------------------------------
__device__ __forceinline__ void mma16(float* c, const uint32_t* a, const uint32_t* b)
{
    asm volatile(
        "mma.sync.aligned.m16n8k16.row.col.f32.f16.f16.f32 "
        "{%0,%1,%2,%3}, {%4,%5,%6,%7}, {%8,%9}, {%0,%1,%2,%3};\n"
        : "+f"(c[0]), "+f"(c[1]), "+f"(c[2]), "+f"(c[3])
        : "r"(a[0]), "r"(a[1]), "r"(a[2]), "r"(a[3]), "r"(b[0]), "r"(b[1]));
}

__device__ __forceinline__ uint32_t pk_hi(float x0, float x1)
{
    uint32_t r;
    asm("cvt.rn.f16x2.f32 %0, %1, %2;" : "=r"(r) : "f"(x1), "f"(x0));
    return r;
}
__device__ __forceinline__ uint32_t pk_lo(float x0, float x1, uint32_t hi)
{
    __half2 h = *reinterpret_cast<__half2*>(&hi);
    float l0 = x0 - __low2float(h);
    float l1 = x1 - __high2float(h);
    return pk_hi(l0, l1);
}

__device__ __forceinline__ void cpa16(void* smem, const void* gmem)
{
    uint32_t s = (uint32_t)__cvta_generic_to_shared(smem);
    asm volatile("cp.async.cg.shared.global [%0], [%1], 16;\n" :: "r"(s), "l"(gmem));
}
__device__ __forceinline__ void cp_commit()
{
    asm volatile("cp.async.commit_group;\n");
}
template <int N> __device__ __forceinline__ void cp_wait()
{
    asm volatile("cp.async.wait_group %0;\n" :: "n"(N));
}

// ---------------- weight prepack (interleaved-pair layout, fp16 planes) -------
__global__ __launch_bounds__(256) void pack_w(
    const float* __restrict__ W, uint32_t* __restrict__ Wp, int Kh, int N)
{
    const long plane = (long)Kh * N;
    const long total = 2 * plane;
    const int rowlen = 2 * N;
    for (long i = blockIdx.x * blockDim.x + threadIdx.x; i < total;
         i += (long)gridDim.x * blockDim.x) {
        int p = (int)(i / plane);
        long rem = i - (long)p * plane;
        int row = (int)(rem / rowlen);
        int col2 = (int)(rem - (long)row * rowlen);
        int n = col2 >> 1, j = col2 & 1;
        int q = row >> 2, tig = row & 3;
        int kp = q * 8 + tig + 4 * j;
        float x0 = W[(long)(2 * kp) * N + n];
        float x1 = W[(long)(2 * kp + 1) * N + n];
        uint32_t hi = pk_hi(x0, x1);
        Wp[i] = p ? pk_lo(x0, x1, hi) : hi;
    }
}

// fused UV pack: Wuv(k, c) = c<1024 ? W1[k][c] : W1[1024+k][c-1024]
__global__ __launch_bounds__(256) void pack_wuv(
    const float* __restrict__ W1, uint32_t* __restrict__ Wp)
{
    const long plane = 512L * 2048;
    const long total = 2 * plane;
    for (long i = blockIdx.x * blockDim.x + threadIdx.x; i < total;
         i += (long)gridDim.x * blockDim.x) {
        int p = (int)(i / plane);
        long rem = i - (long)p * plane;
        int row = (int)(rem >> 12);
        int col2 = (int)(rem & 4095);
        int n = col2 >> 1, j = col2 & 1;
        int q = row >> 2, tig = row & 3;
        int kp = q * 8 + tig + 4 * j;
        int k0 = 2 * kp, k1 = 2 * kp + 1;
        float x0, x1;
        if (n < 1024) {
            x0 = W1[(long)k0 * 1024 + n];
            x1 = W1[(long)k1 * 1024 + n];
        } else {
            x0 = W1[(long)(1024 + k0) * 1024 + (n - 1024)];
            x1 = W1[(long)(1024 + k1) * 1024 + (n - 1024)];
        }
        uint32_t hi = pk_hi(x0, x1);
        Wp[i] = p ? pk_lo(x0, x1, hi) : hi;
    }
}

// ---------------- batched GEMM (fp16 2-product, 3-stage B pipeline) -----------
// BM=64, BN=128, 256 threads, 2 blocks/SM. A: 2-buf reg-staged; B: 3-stage ring.
#define GEMM_SMEM ((2 * 1280 + 3 * 4224) * 4)
__global__ __launch_bounds__(256, 2) void gemm_f16p(
    const float* __restrict__ A1, const float* __restrict__ A1o,
    int lrpb, long sA1, int K1,
    const float* __restrict__ A2, long sA2,
    const uint32_t* __restrict__ Wp, const float* __restrict__ bias,
    float* __restrict__ C, int Nw, long PKw, int ldc, int Ktot, int do_relu)
{
    extern __shared__ __align__(16) uint32_t sm[];
    uint32_t* As = sm;             // 2 x 1280
    uint32_t* Bs = sm + 2560;      // 3 x 4224

    const int t = threadIdx.x, lane = t & 31, warp = t >> 5;
    const int gid = lane >> 2, tig = lane & 3;
    const int wm = warp >> 2, wn = warp & 3;
    const int m0 = wm * 32, n0w = wn * 32;
    const long bn0 = (long)blockIdx.x * 128;
    const int bm0 = blockIdx.y * 64;
    const int K2 = Ktot - K1;
    const int rmask = (1 << lrpb) - 1;

    const int lrow = t >> 2, lf4 = t & 3;
    const int grow = bm0 + lrow;
    const int b = grow >> lrpb, n = grow & rmask;
    const float* p1 = (A1o && n < 16)
                        ? (A1o + (long)b * 16384 + (long)n * 1024)
                        : (A1 + (long)b * sA1 + (long)n * K1);
    const float* p2 = A2 ? (A2 + (long)b * sA2 + (long)n * K2) : p1;

    float4 ra0, ra1;
    auto ldgA = [&](int k0) {
        const float* rp = (k0 < K1) ? (p1 + k0) : (p2 + (k0 - K1));
        ra0 = *(const float4*)(rp + lf4 * 4);
        ra1 = *(const float4*)(rp + lf4 * 4 + 16);
    };
    auto stsA = [&](int buf) {
        uint32_t* Ah = As + buf * 1280 + lrow * 20;
        const int w = lf4 * 2;
        Ah[w]     = pk_hi(ra0.x, ra0.y);
        Ah[w + 1] = pk_hi(ra0.z, ra0.w);
        Ah[w + 8] = pk_hi(ra1.x, ra1.y);
        Ah[w + 9] = pk_hi(ra1.z, ra1.w);
    };
    auto stageB = [&](int buf, int k0) {
        const int gr0 = k0 >> 2;
#pragma unroll
        for (int i = 0; i < 4; i++) {
            int f = t + i * 256;
            int plane = f >> 9, g = f & 511;
            int rl = g >> 6, c4 = (g & 63) * 4;
            cpa16(&Bs[buf * 4224 + plane * 2112 + rl * 264 + c4],
                  Wp + plane * PKw + (long)(gr0 + rl) * (2 * Nw) + bn0 * 2 + c4);
        }
        cp_commit();
    };

    float c[2][4][4];
#pragma unroll
    for (int mt = 0; mt < 2; mt++)
#pragma unroll
        for (int nt = 0; nt < 4; nt++)
#pragma unroll
            for (int e = 0; e < 4; e++) c[mt][nt][e] = 0.f;

    const int nIter = Ktot >> 5;
    ldgA(0);
    stageB(0, 0);
    if (nIter > 1) stageB(1, 32); else cp_commit();
    stsA(0);

    for (int i = 0; i < nIter; i++) {
        const int k0 = i << 5;
        const bool more = (i + 1 < nIter);
        cp_wait<1>();
        __syncthreads();
        if (more) ldgA(k0 + 32);
        if (i + 2 < nIter) stageB((i + 2) % 3, k0 + 64); else cp_commit();

        const uint32_t* Ah = As + (i & 1) * 1280;
        const uint32_t* Bh = Bs + (i % 3) * 4224;
        const uint32_t* Bl = Bh + 2112;
#pragma unroll
        for (int k16 = 0; k16 < 2; k16++) {
            const int kb = k16 * 8;
            uint32_t ah[2][4];
#pragma unroll
            for (int mt = 0; mt < 2; mt++) {
                int r0 = (m0 + mt * 16 + gid) * 20;
                int r1 = r0 + 160;
                ah[mt][0] = Ah[r0 + kb + tig];
                ah[mt][1] = Ah[r1 + kb + tig];
                ah[mt][2] = Ah[r0 + kb + tig + 4];
                ah[mt][3] = Ah[r1 + kb + tig + 4];
            }
            const int brow = (k16 * 4 + tig) * 264;
#pragma unroll
            for (int nt = 0; nt < 4; nt++) {
                int cw = brow + 2 * (n0w + nt * 8 + gid);
                uint2 b2h = *(const uint2*)&Bh[cw];
                uint2 b2l = *(const uint2*)&Bl[cw];
                uint32_t bh[2] = { b2h.x, b2h.y };
                uint32_t bl[2] = { b2l.x, b2l.y };
#pragma unroll
                for (int mt = 0; mt < 2; mt++) {
                    mma16(c[mt][nt], ah[mt], bh);
                    mma16(c[mt][nt], ah[mt], bl);
                }
            }
        }
        if (more) stsA((i + 1) & 1);
    }

#pragma unroll
    for (int mt = 0; mt < 2; mt++) {
#pragma unroll
        for (int nt = 0; nt < 4; nt++) {
            long col = bn0 + n0w + nt * 8 + 2 * tig;
            float b0v = 0.f, b1v = 0.f;
            if (bias) { b0v = bias[col]; b1v = bias[col + 1]; }
            int r = bm0 + m0 + mt * 16 + gid;
            float v0 = c[mt][nt][0] + b0v, v1 = c[mt][nt][1] + b1v;
            float v2 = c[mt][nt][2] + b0v, v3 = c[mt][nt][3] + b1v;
            if (do_relu) {
                v0 = fmaxf(v0, 0.f); v1 = fmaxf(v1, 0.f);
                v2 = fmaxf(v2, 0.f); v3 = fmaxf(v3, 0.f);
            }
            *(float2*)&C[(long)r * ldc + col]       = make_float2(v0, v1);
            *(float2*)&C[(long)(r + 8) * ldc + col] = make_float2(v2, v3);
        }
    }
}

// ---------------- fused pair MLP (fp16 2-product, 3-stage B pipeline) ---------
// BM=128, BN=256, grid (8, 2, 32), 512 threads.
#define PAIR_SMEM ((5120 + 3 * 8320 + 512 + 1024) * 4)
__global__ __launch_bounds__(512, 1) void pair_mlp_mma(
    const float* __restrict__ UV, const float* __restrict__ b1,
    const uint32_t* __restrict__ W2p, const float* __restrict__ b2,
    const float* __restrict__ W3, float* __restrict__ wsum)
{
    extern __shared__ __align__(16) uint32_t sm[];
    uint32_t* As = sm;                     // 2 x 2560
    uint32_t* Bs = sm + 5120;              // 3 x 8320
    float* wpart = (float*)(sm + 5120 + 3 * 8320);
    float* b1s   = (float*)(sm + 5120 + 3 * 8320 + 512);

    const int t = threadIdx.x, lane = t & 31, warp = t >> 5;
    const int gid = lane >> 2, tig = lane & 3;
    const int wm = warp >> 2, wn = warp & 3;
    const int m0 = wm * 32, n0w = wn * 64;
    const int mblk = blockIdx.x, nblk = blockIdx.y, bi = blockIdx.z;
    const int n0blk = nblk * 256;
    const long PK2 = 512L * 512;

    b1s[t] = b1[t];
    b1s[t + 512] = b1[t + 512];
    __syncthreads();

    const int lrow = t >> 2, lf4 = t & 3;
    const int mld = mblk * 128 + lrow;
    const int valid = (mld < MM);
    int xl = 0, yl = 0;
    if (valid) { xl = mld / 63; int rl = mld - 63 * xl; yl = rl + (rl >= xl ? 1 : 0); }
    const float* Urow = UV + ((long)(bi * 64 + xl)) * 2048;
    const float* Vrow = UV + ((long)(bi * 64 + yl)) * 2048 + 1024;

    float4 ru0, ru1, rv0, rv1;
    auto ldgA = [&](int k0) {
        ru0 = *(const float4*)(Urow + k0 + lf4 * 4);
        ru1 = *(const float4*)(Urow + k0 + lf4 * 4 + 16);
        rv0 = *(const float4*)(Vrow + k0 + lf4 * 4);
        rv1 = *(const float4*)(Vrow + k0 + lf4 * 4 + 16);
    };
    auto stsA = [&](int buf, int k0) {
        float4 rb0 = *(const float4*)&b1s[k0 + lf4 * 4];
        float4 rb1 = *(const float4*)&b1s[k0 + lf4 * 4 + 16];
        float4 h0, h1;
        h0.x = fmaxf(ru0.x + rv0.x + rb0.x, 0.f);
        h0.y = fmaxf(ru0.y + rv0.y + rb0.y, 0.f);
        h0.z = fmaxf(ru0.z + rv0.z + rb0.z, 0.f);
        h0.w = fmaxf(ru0.w + rv0.w + rb0.w, 0.f);
        h1.x = fmaxf(ru1.x + rv1.x + rb1.x, 0.f);
        h1.y = fmaxf(ru1.y + rv1.y + rb1.y, 0.f);
        h1.z = fmaxf(ru1.z + rv1.z + rb1.z, 0.f);
        h1.w = fmaxf(ru1.w + rv1.w + rb1.w, 0.f);
        if (!valid) {
            h0 = make_float4(0.f, 0.f, 0.f, 0.f);
            h1 = make_float4(0.f, 0.f, 0.f, 0.f);
        }
        uint32_t* Ah = As + buf * 2560 + lrow * 20;
        const int w = lf4 * 2;
        Ah[w]     = pk_hi(h0.x, h0.y);
        Ah[w + 1] = pk_hi(h0.z, h0.w);
        Ah[w + 8] = pk_hi(h1.x, h1.y);
        Ah[w + 9] = pk_hi(h1.z, h1.w);
    };
    auto stageB = [&](int buf, int k0) {
        const int gr0 = k0 >> 2;
#pragma unroll
        for (int i = 0; i < 4; i++) {
            int f = t + i * 512;
            int plane = f >> 10, g = f & 1023;
            int rl = g >> 7, c4 = (g & 127) * 4;
            cpa16(&Bs[buf * 8320 + plane * 4160 + rl * 520 + c4],
                  W2p + plane * PK2 + (long)(gr0 + rl) * 1024 + n0blk * 2 + c4);
        }
        cp_commit();
    };

    float c[2][8][4];
#pragma unroll
    for (int mt = 0; mt < 2; mt++)
#pragma unroll
        for (int nt = 0; nt < 8; nt++)
#pragma unroll
            for (int e = 0; e < 4; e++) c[mt][nt][e] = 0.f;

    ldgA(0);
    stageB(0, 0);
    stageB(1, 32);
    stsA(0, 0);

    for (int i = 0; i < 32; i++) {
        const int k0 = i << 5;
        const bool more = (i + 1 < 32);
        cp_wait<1>();
        __syncthreads();
        if (more) ldgA(k0 + 32);
        if (i + 2 < 32) stageB((i + 2) % 3, k0 + 64); else cp_commit();

        const uint32_t* Ah = As + (i & 1) * 2560;
        const uint32_t* Bh = Bs + (i % 3) * 8320;
        const uint32_t* Bl = Bh + 4160;
#pragma unroll
        for (int k16 = 0; k16 < 2; k16++) {
            const int kb = k16 * 8;
            uint32_t ah[2][4];
#pragma unroll
            for (int mt = 0; mt < 2; mt++) {
                int r0 = (m0 + mt * 16 + gid) * 20;
                int r1 = r0 + 160;
                ah[mt][0] = Ah[r0 + kb + tig];
                ah[mt][1] = Ah[r1 + kb + tig];
                ah[mt][2] = Ah[r0 + kb + tig + 4];
                ah[mt][3] = Ah[r1 + kb + tig + 4];
            }
            const int brow = (k16 * 4 + tig) * 520;
#pragma unroll
            for (int nt = 0; nt < 8; nt++) {
                int cw = brow + 2 * (n0w + nt * 8 + gid);
                uint2 b2h = *(const uint2*)&Bh[cw];
                uint2 b2l = *(const uint2*)&Bl[cw];
                uint32_t bh[2] = { b2h.x, b2h.y };
                uint32_t bl[2] = { b2l.x, b2l.y };
#pragma unroll
                for (int mt = 0; mt < 2; mt++) {
                    mma16(c[mt][nt], ah[mt], bh);
                    mma16(c[mt][nt], ah[mt], bl);
                }
            }
        }
        if (more) stsA((i + 1) & 1, k0 + 32);
    }

    float rp[4] = { 0.f, 0.f, 0.f, 0.f };
#pragma unroll
    for (int mt = 0; mt < 2; mt++) {
#pragma unroll
        for (int nt = 0; nt < 8; nt++) {
            int col = n0blk + n0w + nt * 8 + 2 * tig;
            float b2a = b2[col], b2b = b2[col + 1];
            float w3a = W3[col], w3b = W3[col + 1];
            rp[2 * mt + 0] += fmaxf(c[mt][nt][0] + b2a, 0.f) * w3a
                            + fmaxf(c[mt][nt][1] + b2b, 0.f) * w3b;
            rp[2 * mt + 1] += fmaxf(c[mt][nt][2] + b2a, 0.f) * w3a
                            + fmaxf(c[mt][nt][3] + b2b, 0.f) * w3b;
        }
    }
#pragma unroll
    for (int e = 0; e < 4; e++) {
        float v = rp[e];
        v += __shfl_xor_sync(0xffffffffu, v, 1);
        v += __shfl_xor_sync(0xffffffffu, v, 2);
        int mt = e >> 1, o = e & 1;
        if (tig == 0) wpart[(m0 + mt * 16 + o * 8 + gid) * 4 + wn] = v;
    }
    __syncthreads();
    if (t < 128) {
        float s = wpart[t * 4 + 0] + wpart[t * 4 + 1]
                + wpart[t * 4 + 2] + wpart[t * 4 + 3];
        wsum[(long)nblk * (BB * 1024) + bi * 1024 + mblk * 128 + t] = s;
    }
}

// ---------------- sigmoid over summed W3 partials ------------------------------
__global__ __launch_bounds__(1024) void sigmoid_k(
    const float* __restrict__ wsum, const float* __restrict__ b3,
    float* __restrict__ Aout)
{
    const int bi = blockIdx.x, m = threadIdx.x;
    if (m < MM) {
        float s = wsum[bi * 1024 + m] + wsum[BB * 1024 + bi * 1024 + m] + b3[0];
        int x = m / 63; int r = m - 63 * x; int y = r + (r >= x ? 1 : 0);
        Aout[(bi * 16 + x) * 64 + y] = 1.f / (1.f + expf(-s));
    }
}

// ---------------- msg_h = A @ O ------------------------------------------------
__global__ __launch_bounds__(256) void msg_h_k(
    const float* __restrict__ Ag, const float* __restrict__ O, float* __restrict__ mh)
{
    __shared__ float As[NH * NN];
    const int b = blockIdx.y, t = threadIdx.x;
#pragma unroll
    for (int i = 0; i < 4; i++) As[t + 256 * i] = Ag[b * NH * NN + t + 256 * i];
    __syncthreads();
    const int j = blockIdx.x * 256 + t;
    float acc[NH];
#pragma unroll
    for (int x = 0; x < NH; x++) acc[x] = 0.f;
    for (int n = 0; n < NN; n++) {
        float o = O[((long)(b * NN + n)) * 1024 + j];
#pragma unroll
        for (int x = 0; x < NH; x++) acc[x] += As[x * NN + n] * o;
    }
#pragma unroll
    for (int x = 0; x < NH; x++) mh[((long)(b * NH + x)) * 1024 + j] = acc[x];
}

// ---------------- msg_o = A^T @ S ----------------------------------------------
__global__ __launch_bounds__(256) void msg_o_k(
    const float* __restrict__ Ag, const float* __restrict__ Sm, float* __restrict__ mo)
{
    __shared__ float As[NH * NN];
    const int b = blockIdx.y, t = threadIdx.x;
#pragma unroll
    for (int i = 0; i < 4; i++) As[t + 256 * i] = Ag[b * NH * NN + t + 256 * i];
    __syncthreads();
    const int j = blockIdx.x * 256 + t;
    float s[NH];
#pragma unroll
    for (int x = 0; x < NH; x++) s[x] = Sm[((long)(b * NH + x)) * 1024 + j];
    for (int n = 0; n < NN; n++) {
        float acc = 0.f;
#pragma unroll
        for (int x = 0; x < NH; x++) acc += As[x * NN + n] * s[x];
        mo[((long)(b * NN + n)) * 1024 + j] = acc;
    }
}

// ---------------- output assembly ----------------------------------------------
__device__ __forceinline__ float lis_f(float s) {
    return 8.3f / (1.f + expf(12.f - 10.f * s));
}

__global__ __launch_bounds__(128) void out_kernel(
    const float* __restrict__ enc, const float* __restrict__ Ag,
    const float* __restrict__ coords, const int* __restrict__ labels,
    const float* __restrict__ scores, float* __restrict__ out)
{
    const int b = blockIdx.y, m = blockIdx.x, t = threadIdx.x;
    const int x = m / 63; const int r = m - 63 * x; const int y = r + (r >= x ? 1 : 0);
    const long row = (long)b * MM + m;

    const float4* ex = (const float4*)(enc + ((long)(b * NN + x)) * RR);
    const float4* ey = (const float4*)(enc + ((long)(b * NN + y)) * RR);
    float4* po = (float4*)(out + row * 2048);
#pragma unroll
    for (int i = 0; i < 4; i++) {
        int q = t + (i << 7);
        po[q] = (q < 256) ? ex[q] : ey[q - 256];
    }
    if (t < 4)        out[OFF_BH + row * 4 + t]       = coords[(b * NN + x) * 4 + t];
    else if (t < 8)   out[OFF_BO + row * 4 + (t - 4)] = coords[(b * NN + y) * 4 + (t - 4)];

    const int lbl = labels[b * NN + y];
    const float val = Ag[(b * NH + x) * NN + y] *
                      lis_f(scores[b * NN + x]) * lis_f(scores[b * NN + y]);
    for (int c = t; c < NCLS; c += 128)
        out[OFF_PR + row * (long)NCLS + c] = (c == lbl) ? val : 0.f;
}

// ---------------- host orchestration -------------------------------------------
extern "C" void kernel_launch(void* const* d_in, const int* in_sizes, int n_in,
                              void* d_out, int out_size)
{
    const float* box_features = (const float*)d_in[0];
    const float* box_coords   = (const float*)d_in[1];
    const int*   box_labels   = (const int*)  d_in[2];
    const float* box_scores   = (const float*)d_in[3];
    const float* W1  = (const float*)d_in[4];
    const float* b1  = (const float*)d_in[5];
    const float* W2  = (const float*)d_in[6];
    const float* b2  = (const float*)d_in[7];
    const float* W3  = (const float*)d_in[8];
    const float* b3  = (const float*)d_in[9];
    const float* Ws  = (const float*)d_in[10];
    const float* bs  = (const float*)d_in[11];
    const float* Wo  = (const float*)d_in[12];
    const float* bo  = (const float*)d_in[13];
    const float* Wsu = (const float*)d_in[14];
    const float* Wou = (const float*)d_in[15];
    float* out = (float*)d_out;

    float *encA, *encB, *UV, *O, *mh, *eh, *Sb, *mo, *Ag, *wsum;
    uint32_t *W1p, *W2p, *Wop, *Wsp, *Wsup, *Woup;
    cudaGetSymbolAddress((void**)&encA, g_encA);
    cudaGetSymbolAddress((void**)&encB, g_encB);
    cudaGetSymbolAddress((void**)&UV,   g_UV);
    cudaGetSymbolAddress((void**)&O,    g_O);
    cudaGetSymbolAddress((void**)&mh,   g_mh);
    cudaGetSymbolAddress((void**)&eh,   g_eh);
    cudaGetSymbolAddress((void**)&Sb,   g_S);
    cudaGetSymbolAddress((void**)&mo,   g_mo);
    cudaGetSymbolAddress((void**)&Ag,   g_A);
    cudaGetSymbolAddress((void**)&wsum, g_wsum);
    cudaGetSymbolAddress((void**)&W1p,  g_W1p);
    cudaGetSymbolAddress((void**)&W2p,  g_W2p);
    cudaGetSymbolAddress((void**)&Wop,  g_Wop);
    cudaGetSymbolAddress((void**)&Wsp,  g_Wsp);
    cudaGetSymbolAddress((void**)&Wsup, g_Wsup);
    cudaGetSymbolAddress((void**)&Woup, g_Woup);

    cudaFuncSetAttribute(gemm_f16p,
                         cudaFuncAttributeMaxDynamicSharedMemorySize, GEMM_SMEM);
    cudaFuncSetAttribute(pair_mlp_mma,
                         cudaFuncAttributeMaxDynamicSharedMemorySize, PAIR_SMEM);

    // aux stream + events (created per call; never destroyed during capture)
    cudaStream_t s1;
    cudaStreamCreateWithFlags(&s1, cudaStreamNonBlocking);
    cudaEvent_t ev[8];
    for (int i = 0; i < 8; i++)
        cudaEventCreateWithFlags(&ev[i], cudaEventDisableTiming);

    // ---- startup: only W1p/W2p/Wop needed early; defer the rest to s1 ----
    cudaEventRecord(ev[0], 0);
    cudaStreamWaitEvent(s1, ev[0], 0);
    cudaMemcpyAsync(encA, box_features, (size_t)BB * NN * RR * 4,
                    cudaMemcpyDeviceToDevice, 0);
    pack_wuv<<<512, 256>>>(W1, W1p);
    pack_w<<<256, 256, 0, s1>>>(W2, W2p, 512, 512);
    cudaEventRecord(ev[1], s1);          // W2p ready
    pack_w<<<256, 256, 0, s1>>>(Wo, Wop, 512, 1024);

    const long sEnc = (long)NN * RR;   // 65536
    const long sH   = (long)NH * RR;   // 16384
    const float* NUL = (const float*)0;

    for (int it = 0; it < 2; it++) {
        float* encIn  = (it == 0) ? encA : encB;
        float* encOut = (it == 0) ? encB : encA;
        cudaEvent_t evF = ev[2 + 2 * it], evJ = ev[3 + 2 * it];

        // fork: O gemm on s1 (depends only on encIn)
        cudaEventRecord(evF, 0);
        cudaStreamWaitEvent(s1, evF, 0);
        gemm_f16p<<<dim3(8, 32), 256, GEMM_SMEM, s1>>>(
            encIn, NUL, 6, sEnc, 1024, NUL, 0,
            Wop, bo, O, 1024, 512L * 1024, 1024, 1024, 1);

        // iter 0: deferred packs on s1 — hidden behind the pair MLP on s0
        if (it == 0) {
            pack_w<<<512, 256, 0, s1>>>(Wsu, Wsup, 1024, 1024);
            pack_w<<<256, 256, 0, s1>>>(Ws, Wsp, 512, 1024);
            pack_w<<<512, 256, 0, s1>>>(Wou, Woup, 1024, 1024);
        }

        // s0: UV gemm -> pair MLP -> sigmoid
        gemm_f16p<<<dim3(16, 32), 256, GEMM_SMEM>>>(
            encIn, NUL, 6, sEnc, 1024, NUL, 0,
            W1p, NUL, UV, 2048, 512L * 2048, 2048, 1024, 0);
        if (it == 0) cudaStreamWaitEvent(0, ev[1], 0);   // W2p ready
        pair_mlp_mma<<<dim3(8, 2, BB), 512, PAIR_SMEM>>>(
            UV, b1, W2p, b2, W3, wsum);
        sigmoid_k<<<BB, 1024>>>(wsum, b3, Ag);

        // join before msg_h (needs A and O; also orders deferred packs)
        cudaEventRecord(evJ, s1);
        cudaStreamWaitEvent(0, evJ, 0);

        msg_h_k<<<dim3(4, BB), 256>>>(Ag, O, mh);
        gemm_f16p<<<dim3(8, 8), 256, GEMM_SMEM>>>(
            encIn, NUL, 4, sEnc, 1024, mh, sH,
            Wsup, NUL, eh, 1024, 1024L * 1024, 1024, 2048, 0);
        gemm_f16p<<<dim3(8, 8), 256, GEMM_SMEM>>>(
            eh, NUL, 4, sH, 1024, NUL, 0,
            Wsp, bs, Sb, 1024, 512L * 1024, 1024, 1024, 1);
        msg_o_k<<<dim3(4, BB), 256>>>(Ag, Sb, mo);
        // splice handled via A1o override: rows n<16 read eh instead of encIn
        gemm_f16p<<<dim3(8, 32), 256, GEMM_SMEM>>>(
            encIn, eh, 6, sEnc, 1024, mo, sEnc,
            Woup, NUL, encOut, 1024, 1024L * 1024, 1024, 2048, 0);
    }

    out_kernel<<<dim3(MM, BB), 128>>>(encA, Ag, box_coords, box_labels,
                                      box_scores, out);
    (void)in_sizes; (void)n_in; (void)out_size;
}